// round 12
// baseline (speedup 1.0000x reference)
#include <cuda_runtime.h>
#include <cuda.h>
#include <math.h>
#include <stdint.h>

#define BATCH 64
#define EDIM 1024
#define HDIM 1024
#define FDIM 2048
#define VDIM 32000
#define NLAYER 8
#define BH (BATCH * HDIM)

// ---------------- scratch (no allocation allowed) ----------------
__device__ __align__(16) float g_ain[NLAYER * BATCH * EDIM];   // layer inputs
__device__ __align__(16) float g_buf0[BATCH * HDIM];
__device__ __align__(16) float g_buf1[BATCH * HDIM];
__device__ __align__(16) float g_gh[NLAYER * BATCH * 3 * HDIM];
__device__ __align__(16) float g_hplus[NLAYER * BATCH * HDIM];
__device__ __align__(16) float g_part[64 * BATCH * 48];
__device__ int g_bar2[4];
__device__ int g_flag[64];   // split-K partials ready (z=1 -> z=0)
__device__ int g_rdy[64];    // ain[l+1] group ready (z=0 -> all)
__device__ int g_ack[64];    // partials consumed (z=0 -> z=1)

// ---------------- ptx helpers ----------------
__device__ __forceinline__ uint32_t tfb(float x) { return __float_as_uint(x); }

__device__ __forceinline__ void cp16(uint32_t saddr, const void* g) {
    asm volatile("cp.async.cg.shared.global [%0], [%1], 16;\n" ::"r"(saddr), "l"(g));
}
__device__ __forceinline__ void cp_commit() { asm volatile("cp.async.commit_group;\n"); }
template <int N>
__device__ __forceinline__ void cp_wait() { asm volatile("cp.async.wait_group %0;\n" ::"n"(N)); }

__device__ __forceinline__ void mbar_init(uint32_t mbar, uint32_t cnt) {
    asm volatile("mbarrier.init.shared.b64 [%0], %1;" ::"r"(mbar), "r"(cnt) : "memory");
}
__device__ __forceinline__ void mbar_expect(uint32_t mbar, uint32_t bytes) {
    asm volatile("mbarrier.arrive.expect_tx.shared.b64 _, [%0], %1;"
                 ::"r"(mbar), "r"(bytes) : "memory");
}
__device__ __forceinline__ void mbar_arrive(uint32_t mbar) {
    asm volatile("mbarrier.arrive.shared.b64 _, [%0];" ::"r"(mbar) : "memory");
}
__device__ __forceinline__ void mbar_wait(uint32_t mbar, uint32_t parity) {
    asm volatile(
        "{\n\t.reg .pred P;\n"
        "LW_%=:\n\t"
        "mbarrier.try_wait.parity.acquire.cta.shared::cta.b64 P, [%0], %1, 0x989680;\n\t"
        "@P bra LD_%=;\n\t"
        "bra LW_%=;\n"
        "LD_%=:\n\t}"
        ::"r"(mbar), "r"(parity) : "memory");
}
__device__ __forceinline__ void tma3(uint32_t dst, const CUtensorMap* map,
                                     int x, int y, int z, uint32_t mbar) {
    asm volatile(
        "cp.async.bulk.tensor.3d.shared::cta.global.tile.mbarrier::complete_tx::bytes "
        "[%0], [%1, {%2, %3, %4}], [%5];"
        ::"r"(dst), "l"(map), "r"(x), "r"(y), "r"(z), "r"(mbar) : "memory");
}
__device__ __forceinline__ void tma4(uint32_t dst, const CUtensorMap* map,
                                     int x, int y, int z, int w, uint32_t mbar) {
    asm volatile(
        "cp.async.bulk.tensor.4d.shared::cta.global.tile.mbarrier::complete_tx::bytes "
        "[%0], [%1, {%2, %3, %4, %5}], [%6];"
        ::"r"(dst), "l"(map), "r"(x), "r"(y), "r"(z), "r"(w), "r"(mbar) : "memory");
}
__device__ __forceinline__ void fence_async() {
    asm volatile("fence.proxy.async;" ::: "memory");
}

__device__ __forceinline__ void mma8(float* c, uint32_t a0, uint32_t a1, uint32_t a2,
                                     uint32_t a3, uint32_t b0, uint32_t b1) {
    asm volatile(
        "mma.sync.aligned.m16n8k8.row.col.f32.tf32.tf32.f32 "
        "{%0,%1,%2,%3}, {%4,%5,%6,%7}, {%8,%9}, {%0,%1,%2,%3};\n"
        : "+f"(c[0]), "+f"(c[1]), "+f"(c[2]), "+f"(c[3])
        : "r"(a0), "r"(a1), "r"(a2), "r"(a3), "r"(b0), "r"(b1));
}

// ---------------- embed (into ain[0]) + flag init ----------------
__global__ void embed_relu_kernel(const float* __restrict__ emb,
                                  const int* __restrict__ x,
                                  float* __restrict__ ain0) {
    if (blockIdx.x == 0) {
        const int t = threadIdx.x;
        if (t < 4) g_bar2[t] = 0;
        else if (t >= 16 && t < 80) g_flag[t - 16] = 0;
        else if (t >= 80 && t < 144) g_rdy[t - 80] = 0;
        else if (t >= 144 && t < 208) g_ack[t - 144] = 0;
    }
    const int b = blockIdx.x;
    const int row = x[b];
    const float* src = emb + (size_t)row * EDIM;
    float* dst = ain0 + (size_t)b * EDIM;
    for (int e = threadIdx.x; e < EDIM; e += blockDim.x) {
        float v = src[e];
        dst[e] = v > 0.f ? v : 0.f;
    }
}

// ---------------- persistent attention chain (cp.async, 64 blocks) ----------------
__global__ __launch_bounds__(256) void attn_chain(
    const float* __restrict__ feature, const float* __restrict__ attention,
    const float* __restrict__ mapW, const float* __restrict__ mapb,
    const float* __restrict__ aiW, const float* __restrict__ aib,
    const float* __restrict__ ahW, const float* __restrict__ ahb,
    const float* __restrict__ aoW, const float* __restrict__ aob,
    float* __restrict__ buf0, float* __restrict__ buf1,
    const float* __restrict__ hiddens, float* __restrict__ hplus) {
    constexpr int S = 3, LDT = 36, BN = 16;
    __shared__ float As[S * 64 * LDT];
    __shared__ float Ws[S * BN * LDT];

    const float* Aptr[4] = {feature, buf0, buf1, buf0};
    const float* Wptr[4] = {mapW, aiW, ahW, aoW};
    const float* bptr[4] = {mapb, aib, ahb, aob};
    float* optr[3] = {buf0, buf1, buf0};
    const int Ks[4] = {FDIM, HDIM, HDIM, HDIM};

    const int tid = threadIdx.x, lane = tid & 31, warp = tid >> 5;
    const int wm = warp & 3, wn = warp >> 2;
    const int r = lane >> 2, kk = lane & 3;
    const int nBlock = blockIdx.x * BN;

    const uint32_t sA = (uint32_t)__cvta_generic_to_shared(As);
    const uint32_t sW = (uint32_t)__cvta_generic_to_shared(Ws);

    for (int layer = 0; layer < 4; layer++) {
        const float* A = Aptr[layer];
        const float* W = Wptr[layer];
        const int K = Ks[layer];
        const int nK = K / 32;

        auto issue = [&](int st, int k0) {
#pragma unroll
            for (int t = 0; t < 2; t++) {
                const int idx = tid + t * 256;
                const int m = idx >> 3, k4 = idx & 7;
                cp16(sA + (uint32_t)(((st * 64 + m) * LDT + k4 * 4) * 4),
                     A + (size_t)m * K + k0 + k4 * 4);
            }
            if (tid < BN * 8) {
                const int wr = tid >> 3, k4 = tid & 7;
                cp16(sW + (uint32_t)(((st * BN + wr) * LDT + k4 * 4) * 4),
                     W + (size_t)(nBlock + wr) * K + k0 + k4 * 4);
            }
        };

#pragma unroll
        for (int p = 0; p < S - 1; p++) {
            if (p < nK) issue(p, p * 32);
            cp_commit();
        }

        float acc[4] = {0.f, 0.f, 0.f, 0.f};
        for (int kt = 0; kt < nK; kt++) {
            cp_wait<S - 2>();
            __syncthreads();
            const int pf = kt + S - 1;
            if (pf < nK) issue(pf % S, pf * 32);
            cp_commit();
            const float* a_ = As + (kt % S) * 64 * LDT;
            const float* w_ = Ws + (kt % S) * BN * LDT;
#pragma unroll
            for (int s = 0; s < 4; s++) {
                const int col = s * 8 + kk;
                const uint32_t a0 = tfb(a_[(wm * 16 + r) * LDT + col]);
                const uint32_t a1 = tfb(a_[(wm * 16 + r + 8) * LDT + col]);
                const uint32_t a2 = tfb(a_[(wm * 16 + r) * LDT + col + 4]);
                const uint32_t a3 = tfb(a_[(wm * 16 + r + 8) * LDT + col + 4]);
                const int n = wn * 8 + r;
                mma8(acc, a0, a1, a2, a3, tfb(w_[n * LDT + col]),
                     tfb(w_[n * LDT + col + 4]));
            }
        }
        cp_wait<0>();

        const int row0 = wm * 16 + r;
        const int col = nBlock + wn * 8 + 2 * kk;
        const float b0v = bptr[layer][col], b1v = bptr[layer][col + 1];
        float v0 = fmaxf(acc[0] + b0v, 0.f), v1 = fmaxf(acc[1] + b1v, 0.f);
        float v2 = fmaxf(acc[2] + b0v, 0.f), v3 = fmaxf(acc[3] + b1v, 0.f);
        if (layer == 0) {
            v0 += attention[(size_t)row0 * HDIM + col];
            v1 += attention[(size_t)row0 * HDIM + col + 1];
            v2 += attention[(size_t)(row0 + 8) * HDIM + col];
            v3 += attention[(size_t)(row0 + 8) * HDIM + col + 1];
        }
        if (layer < 3) {
            float* o = optr[layer];
            *reinterpret_cast<float2*>(o + (size_t)row0 * HDIM + col) = make_float2(v0, v1);
            *reinterpret_cast<float2*>(o + (size_t)(row0 + 8) * HDIM + col) = make_float2(v2, v3);
        } else {
#pragma unroll
            for (int l = 0; l < NLAYER; l++) {
                const size_t b0i = (size_t)l * BH + (size_t)row0 * HDIM + col;
                const size_t b1i = (size_t)l * BH + (size_t)(row0 + 8) * HDIM + col;
                float2 h0 = *reinterpret_cast<const float2*>(hiddens + b0i);
                float2 h8 = *reinterpret_cast<const float2*>(hiddens + b1i);
                *reinterpret_cast<float2*>(hplus + b0i) = make_float2(h0.x + v0, h0.y + v1);
                *reinterpret_cast<float2*>(hplus + b1i) = make_float2(h8.x + v2, h8.y + v3);
            }
            fence_async();
        }

        if (layer < 3) {
            __threadfence();
            __syncthreads();
            if (tid == 0) {
                atomicAdd(&g_bar2[layer], 1);
                while (atomicAdd(&g_bar2[layer], 0) < (int)gridDim.x) __nanosleep(32);
            }
            __syncthreads();
        }
    }
}

// ---------------- TMA tensormap GEMM: C[64,N] = A @ W^T + bias (BN=128, K=1024) -----
__global__ __launch_bounds__(256) void gemm_tma(
    const __grid_constant__ CUtensorMap mapA,
    const __grid_constant__ CUtensorMap mapW,
    const float* __restrict__ bias, float* __restrict__ out,
    int N, int biasStride) {
    constexpr int BN = 128;
    constexpr int STG = (64 + BN) * 32 * 4;
    extern __shared__ float sm[];
    const uint32_t sb = (uint32_t)__cvta_generic_to_shared(sm);
    const uint32_t tiles = sb + 1024;

    const int tid = threadIdx.x, lane = tid & 31, warp = tid >> 5;
    const int wm = warp & 3, wn = warp >> 2;
    const int r = lane >> 2, kk = lane & 3;
    const int nBlock = blockIdx.x * BN;
    const int layer = blockIdx.y;

    bias += (size_t)layer * biasStride;
    out += (size_t)layer * BATCH * N;

    if (tid == 0) {
#pragma unroll
        for (int s = 0; s < 4; s++) mbar_init(sb + s * 8, 1);
    }
    __syncthreads();

    auto fill = [&](int s, int kt) {
        if (tid == 0) {
            const uint32_t mb = sb + s * 8;
            mbar_expect(mb, STG);
            const uint32_t dA = tiles + s * STG;
            tma3(dA, &mapA, kt * 32, 0, layer, mb);
            tma3(dA + 64 * 128, &mapW, kt * 32, nBlock, layer, mb);
        }
    };
    fill(0, 0); fill(1, 1); fill(2, 2);

    float acc[8][4];
#pragma unroll
    for (int i = 0; i < 8; i++)
#pragma unroll
        for (int j = 0; j < 4; j++) acc[i][j] = 0.f;

    const int swz = r << 2;
    for (int kt = 0; kt < 32; kt++) {
        if (kt + 3 < 32) fill((kt + 3) & 3, kt + 3);
        const int s = kt & 3;
        mbar_wait(sb + s * 8, (kt >> 2) & 1);
        const float* a_ = sm + 256 + s * (STG / 4);
        const float* w_ = a_ + 64 * 32;
#pragma unroll
        for (int q = 0; q < 4; q++) {
            const int col = (q * 8 + kk) ^ swz;
            const int col4 = col ^ 4;
            const int m0 = wm * 16 + r;
            const uint32_t a0 = tfb(a_[m0 * 32 + col]);
            const uint32_t a1 = tfb(a_[(m0 + 8) * 32 + col]);
            const uint32_t a2 = tfb(a_[m0 * 32 + col4]);
            const uint32_t a3 = tfb(a_[(m0 + 8) * 32 + col4]);
#pragma unroll
            for (int nt = 0; nt < 8; nt++) {
                const int n = wn * 64 + nt * 8 + r;
                mma8(acc[nt], a0, a1, a2, a3, tfb(w_[n * 32 + col]),
                     tfb(w_[n * 32 + col4]));
            }
        }
        __syncthreads();
    }

    const int row0 = wm * 16 + r;
#pragma unroll
    for (int nt = 0; nt < 8; nt++) {
        const int col = nBlock + wn * 64 + nt * 8 + 2 * kk;
        const float b0v = bias[col], b1v = bias[col + 1];
        *reinterpret_cast<float2*>(out + (size_t)row0 * N + col) =
            make_float2(acc[nt][0] + b0v, acc[nt][1] + b1v);
        *reinterpret_cast<float2*>(out + (size_t)(row0 + 8) * N + col) =
            make_float2(acc[nt][2] + b0v, acc[nt][3] + b1v);
    }
}

// ---------------- persistent fused GRU chain v7: barrier-free dataflow ----------------
// 128 CTAs (64 groups x 2 K-halves). Stage slot s: fullAW[s] (count=2: W-fill + A-fill
// arrive.expect_tx), emptyAW[s] (count=12). W prefetch crosses layers; A fills gated
// on per-group g_rdy flags. No grid barrier.
__global__ __launch_bounds__(384) void gru_chain(
    const __grid_constant__ CUtensorMap mapA,
    const __grid_constant__ CUtensorMap mapW,
    float* __restrict__ ain, float* __restrict__ nh, float* __restrict__ h1,
    const float* __restrict__ gru_bih, const float* __restrict__ gh,
    const float* __restrict__ hplus) {
    constexpr int SLOT = 28672;               // A 16384 + W 12288 bytes
    constexpr int CLD = 50;
    extern __shared__ float sm[];
    const uint32_t sb = (uint32_t)__cvta_generic_to_shared(sm);
    const uint32_t tiles = sb + 1024;
    float* Cs = sm + 256 + 4 * (SLOT / 4);

    const int g = blockIdx.x >> 1;
    const int z = blockIdx.x & 1;
    const int h0 = g * 16;
    const int kBase = z * 512;
    const int tid = threadIdx.x, lane = tid & 31, warp = tid >> 5;
    const int wm = warp & 3, sec = warp >> 2;
    const int r = lane >> 2, kk = lane & 3;
    const int swz = r << 2;

    if (tid == 0) {
#pragma unroll
        for (int s = 0; s < 4; s++) {
            mbar_init(sb + s * 16, 2);        // fullAW (W fill + A fill)
            mbar_init(sb + s * 16 + 8, 12);   // emptyAW (12 warps)
        }
    }
    __syncthreads();

    // W fill: waits slot empty, arrives+expects W bytes. gidx = layer*8+kt (global).
    auto fillW = [&](int gidx) {
        const int s = gidx & 3;
        const int n = gidx >> 2;
        if (n > 0) mbar_wait(sb + s * 16 + 8, (n - 1) & 1);
        const uint32_t mb = sb + s * 16;
        mbar_expect(mb, 12288);
        const int layer = gidx >> 3, kt = gidx & 7;
        const int x0 = kBase + kt * 64;
        const uint32_t dst = tiles + s * SLOT + 16384;
        tma4(dst, &mapW, x0, h0, 0, layer, mb);
        tma4(dst + 6144, &mapW, x0 + 32, h0, 0, layer, mb);
    };
    // A fill: gated on producer-group readiness; arrives+expects A bytes.
    auto fillA = [&](int gidx) {
        const int s = gidx & 3;
        const int layer = gidx >> 3, kt = gidx & 7;
        const int x0 = kBase + kt * 64;
        if (layer > 0) {
            const int gb = x0 >> 4;
#pragma unroll
            for (int j = 0; j < 4; j++)
                while (atomicAdd(&g_rdy[gb + j], 0) < layer) __nanosleep(32);
        }
        const uint32_t mb = sb + s * 16;
        mbar_expect(mb, 16384);
        const uint32_t dst = tiles + s * SLOT;
        tma3(dst, &mapA, x0, 0, layer, mb);
        tma3(dst + 8192, &mapA, x0 + 32, 0, layer, mb);
    };

    if (tid == 0) {
        fillW(0); fillA(0); fillW(1); fillA(1); fillW(2); fillA(2);
    }

    float prev[3];

    for (int layer = 0; layer < NLAYER; layer++) {
        const float* bih = gru_bih + (size_t)layer * 3 * HDIM;
        const float* ghL = gh + (size_t)layer * BATCH * 3 * HDIM;
        const float* hpL = hplus + (size_t)layer * BH;
        float* outh = nh + (size_t)layer * BH;
        float* ainN = ain + (size_t)(layer + 1) * BH;
        const int g0 = layer * 8;

        float acc[2][4] = {{0.f, 0.f, 0.f, 0.f}, {0.f, 0.f, 0.f, 0.f}};
        for (int kt = 0; kt < 8; kt++) {
            if (tid == 0 && kt + 3 < 8) { fillW(g0 + kt + 3); fillA(g0 + kt + 3); }
            const int gidx = g0 + kt;
            const int s = gidx & 3;
            mbar_wait(sb + s * 16, (gidx >> 2) & 1);
            const float* stg = sm + 256 + s * (SLOT / 4);
#pragma unroll
            for (int q = 0; q < 8; q++) {
                const int p = q >> 2;
                const float* a_ = stg + p * 2048;
                const float* w_ = stg + 4096 + p * 1536;
                const int col = ((q & 3) * 8 + kk) ^ swz;
                const int col4 = col ^ 4;
                const int m0 = wm * 16 + r;
                const uint32_t a0 = tfb(a_[m0 * 32 + col]);
                const uint32_t a1 = tfb(a_[(m0 + 8) * 32 + col]);
                const uint32_t a2 = tfb(a_[m0 * 32 + col4]);
                const uint32_t a3 = tfb(a_[(m0 + 8) * 32 + col4]);
#pragma unroll
                for (int nt = 0; nt < 2; nt++) {
                    const int brow = sec * 16 + nt * 8 + r;
                    mma8(acc[nt], a0, a1, a2, a3, tfb(w_[brow * 32 + col]),
                         tfb(w_[brow * 32 + col4]));
                }
            }
            if (lane == 0) mbar_arrive(sb + s * 16 + 8);
        }

        // prefetch next layer's W panels (no recurrence dependency)
        if (tid == 0 && layer < NLAYER - 1) {
            fillW(g0 + 8); fillW(g0 + 9); fillW(g0 + 10);
        }

        const int row0 = wm * 16 + r;

        if (z == 1) {
            // WAR handshake: previous partials must be consumed
            if (tid == 0 && layer > 0) {
                while (atomicAdd(&g_ack[g], 0) < layer) __nanosleep(32);
            }
            __syncthreads();
            float* pg = g_part + (size_t)g * BATCH * 48;
#pragma unroll
            for (int nt = 0; nt < 2; nt++) {
                const int cl = sec * 16 + nt * 8 + 2 * kk;
                *reinterpret_cast<float2*>(pg + row0 * 48 + cl) =
                    make_float2(acc[nt][0], acc[nt][1]);
                *reinterpret_cast<float2*>(pg + (row0 + 8) * 48 + cl) =
                    make_float2(acc[nt][2], acc[nt][3]);
            }
            __threadfence();
            __syncthreads();
            if (tid == 0) {
                atomicExch(&g_flag[g], layer + 1);
                if (layer < NLAYER - 1) { fillA(g0 + 8); fillA(g0 + 9); fillA(g0 + 10); }
            }
        } else {
            if (tid == 0) {
                while (atomicAdd(&g_flag[g], 0) < layer + 1) __nanosleep(32);
            }
            __syncthreads();
            const float* pg = g_part + (size_t)g * BATCH * 48;
#pragma unroll
            for (int nt = 0; nt < 2; nt++) {
                const int cl = sec * 16 + nt * 8 + 2 * kk;
                float2 p0 = *reinterpret_cast<const float2*>(pg + row0 * 48 + cl);
                float2 p8 = *reinterpret_cast<const float2*>(pg + (row0 + 8) * 48 + cl);
                *reinterpret_cast<float2*>(&Cs[row0 * CLD + cl]) =
                    make_float2(acc[nt][0] + p0.x, acc[nt][1] + p0.y);
                *reinterpret_cast<float2*>(&Cs[(row0 + 8) * CLD + cl]) =
                    make_float2(acc[nt][2] + p8.x, acc[nt][3] + p8.y);
            }
            __syncthreads();
            if (tid == 0) atomicExch(&g_ack[g], layer + 1);  // partials consumed

            int t = 0;
            for (int idx = tid; idx < 1024; idx += 384, t++) {
                const int b = idx >> 4, hh = idx & 15;
                const int h = h0 + hh;
                const float ir = Cs[b * CLD + hh] + bih[h];
                const float iz = Cs[b * CLD + 16 + hh] + bih[HDIM + h];
                const float in_ = Cs[b * CLD + 32 + hh] + bih[2 * HDIM + h];
                const float* ghb = ghL + (size_t)b * 3 * HDIM + h;
                const float rr = 1.f / (1.f + expf(-(ir + ghb[0])));
                const float zz = 1.f / (1.f + expf(-(iz + ghb[HDIM])));
                const float nn = tanhf(in_ + rr * ghb[2 * HDIM]);
                const float hp = hpL[(size_t)b * HDIM + h];
                const float o = (1.f - zz) * nn + zz * hp;
                outh[(size_t)b * HDIM + h] = o;
                if (layer == 0) h1[(size_t)b * HDIM + h] = o;
                if (layer < NLAYER - 1) {
                    const float nx = (layer < 2) ? o : (o + prev[t]);
                    ainN[(size_t)b * HDIM + h] = nx;
                }
                prev[t] = o;
            }
            __threadfence();
            __syncthreads();
            if (tid == 0) {
                atomicExch(&g_rdy[g], layer + 1);   // ain[layer+1] cols ready
                if (layer < NLAYER - 1) { fillA(g0 + 8); fillA(g0 + 9); fillA(g0 + 10); }
            }
        }
    }
}

// ---------------- 2-pass online log_softmax ----------------
__global__ __launch_bounds__(1024) void log_softmax_kernel(float* __restrict__ logits) {
    const int b = blockIdx.x;
    float* row = logits + (size_t)b * VDIM;
    __shared__ float smax[32], ssum[32];
    __shared__ float s_lse;
    const int lane = threadIdx.x & 31;
    const int wid = threadIdx.x >> 5;

    float m = -1e30f, s = 0.f;
    const float4* r4 = reinterpret_cast<const float4*>(row);
    for (int v = threadIdx.x; v < VDIM / 4; v += blockDim.x) {
        float4 x = r4[v];
#define ONE(val) { float d = (val) - m; \
        if (d > 0.f) { s = s * __expf(-d) + 1.f; m = (val); } else s += __expf(d); }
        ONE(x.x) ONE(x.y) ONE(x.z) ONE(x.w)
#undef ONE
    }
#pragma unroll
    for (int o = 16; o; o >>= 1) {
        float mo = __shfl_xor_sync(0xffffffffu, m, o);
        float so = __shfl_xor_sync(0xffffffffu, s, o);
        float mn = fmaxf(m, mo);
        s = s * __expf(m - mn) + so * __expf(mo - mn);
        m = mn;
    }
    if (lane == 0) { smax[wid] = m; ssum[wid] = s; }
    __syncthreads();
    if (wid == 0) {
        float mm = (lane < (blockDim.x >> 5)) ? smax[lane] : -1e30f;
        float ss = (lane < (blockDim.x >> 5)) ? ssum[lane] : 0.f;
#pragma unroll
        for (int o = 16; o; o >>= 1) {
            float mo = __shfl_xor_sync(0xffffffffu, mm, o);
            float so = __shfl_xor_sync(0xffffffffu, ss, o);
            float mn = fmaxf(mm, mo);
            ss = ss * __expf(mm - mn) + so * __expf(mo - mn);
            mm = mn;
        }
        if (lane == 0) s_lse = mm + logf(ss);
    }
    __syncthreads();
    const float lse = s_lse;
    float4* w4 = reinterpret_cast<float4*>(row);
    for (int v = threadIdx.x; v < VDIM / 4; v += blockDim.x) {
        float4 x = w4[v];
        x.x -= lse; x.y -= lse; x.z -= lse; x.w -= lse;
        w4[v] = x;
    }
}

// ---------------- host-side tensormap encoding ----------------
typedef CUresult (CUDAAPI* EncFn)(
    CUtensorMap*, CUtensorMapDataType, cuuint32_t, void*,
    const cuuint64_t*, const cuuint64_t*, const cuuint32_t*, const cuuint32_t*,
    CUtensorMapInterleave, CUtensorMapSwizzle, CUtensorMapL2promotion,
    CUtensorMapFloatOOBfill);

static void make_map3(EncFn enc, CUtensorMap* m, const void* p,
                      unsigned long long d0, unsigned long long d1,
                      unsigned long long d2, unsigned int b1) {
    cuuint64_t dims[3] = {d0, d1, d2};
    cuuint64_t strides[2] = {d0 * 4, d0 * d1 * 4};
    cuuint32_t box[3] = {32, b1, 1};
    cuuint32_t es[3] = {1, 1, 1};
    enc(m, CU_TENSOR_MAP_DATA_TYPE_FLOAT32, 3, (void*)p, dims, strides, box, es,
        CU_TENSOR_MAP_INTERLEAVE_NONE, CU_TENSOR_MAP_SWIZZLE_128B,
        CU_TENSOR_MAP_L2_PROMOTION_L2_128B, CU_TENSOR_MAP_FLOAT_OOB_FILL_NONE);
}

static void make_map4_wih(EncFn enc, CUtensorMap* m, const void* p) {
    cuuint64_t dims[4] = {EDIM, HDIM, 3, NLAYER};
    cuuint64_t strides[3] = {(cuuint64_t)EDIM * 4,
                             (cuuint64_t)HDIM * EDIM * 4,
                             (cuuint64_t)3 * HDIM * EDIM * 4};
    cuuint32_t box[4] = {32, 16, 3, 1};
    cuuint32_t es[4] = {1, 1, 1, 1};
    enc(m, CU_TENSOR_MAP_DATA_TYPE_FLOAT32, 4, (void*)p, dims, strides, box, es,
        CU_TENSOR_MAP_INTERLEAVE_NONE, CU_TENSOR_MAP_SWIZZLE_128B,
        CU_TENSOR_MAP_L2_PROMOTION_L2_128B, CU_TENSOR_MAP_FLOAT_OOB_FILL_NONE);
}

// ---------------- launch ----------------
extern "C" void kernel_launch(void* const* d_in, const int* in_sizes, int n_in,
                              void* d_out, int out_size) {
    const float* feature   = (const float*)d_in[0];
    const int*   x         = (const int*)d_in[1];
    const float* attention = (const float*)d_in[2];
    const float* hiddens   = (const float*)d_in[3];
    const float* emb       = (const float*)d_in[4];
    const float* map_W     = (const float*)d_in[5];
    const float* map_b     = (const float*)d_in[6];
    const float* ai_W      = (const float*)d_in[7];
    const float* ai_b      = (const float*)d_in[8];
    const float* ah_W      = (const float*)d_in[9];
    const float* ah_b      = (const float*)d_in[10];
    const float* ao_W      = (const float*)d_in[11];
    const float* ao_b      = (const float*)d_in[12];
    const float* gru_Wih   = (const float*)d_in[13];
    const float* gru_Whh   = (const float*)d_in[14];
    const float* gru_bih   = (const float*)d_in[15];
    const float* gru_bhh   = (const float*)d_in[16];
    const float* out_W     = (const float*)d_in[17];
    const float* out_b     = (const float*)d_in[18];

    float* out = (float*)d_out;
    float* logp = out;
    float* h1   = out + (size_t)BATCH * VDIM;
    float* nh   = h1 + (size_t)BATCH * HDIM;

    float *ain, *buf0, *buf1, *gh, *hplus;
    cudaGetSymbolAddress((void**)&ain, g_ain);
    cudaGetSymbolAddress((void**)&buf0, g_buf0);
    cudaGetSymbolAddress((void**)&buf1, g_buf1);
    cudaGetSymbolAddress((void**)&gh, g_gh);
    cudaGetSymbolAddress((void**)&hplus, g_hplus);

    EncFn enc = nullptr;
    cudaDriverEntryPointQueryResult qr;
    cudaGetDriverEntryPoint("cuTensorMapEncodeTiled", (void**)&enc,
                            cudaEnableDefault, &qr);
    CUtensorMap mW_gh, mA_gh, mW_out, mA_out, mA_ch, mW_ch;
    make_map3(enc, &mW_gh, gru_Whh, HDIM, 3 * HDIM, NLAYER, 128);
    make_map3(enc, &mA_gh, hplus, HDIM, BATCH, NLAYER, 64);
    make_map3(enc, &mW_out, out_W, HDIM, VDIM, 1, 128);
    make_map3(enc, &mA_out, nh + 7 * (size_t)BH, HDIM, BATCH, 1, 64);
    make_map3(enc, &mA_ch, ain, EDIM, BATCH, NLAYER, 64);
    make_map4_wih(enc, &mW_ch, gru_Wih);

    const int SM_TMA = 1024 + 4 * (64 + 128) * 32 * 4;                  // 99328
    const int SM_CH  = 1024 + 4 * 28672 + 64 * 50 * 4;                  // 128512
    cudaFuncSetAttribute((const void*)gemm_tma,
                         cudaFuncAttributeMaxDynamicSharedMemorySize, SM_TMA);
    cudaFuncSetAttribute((const void*)gru_chain,
                         cudaFuncAttributeMaxDynamicSharedMemorySize, SM_CH);

    // 1) embed into ain[0] (+ flag init)
    embed_relu_kernel<<<BATCH, 256>>>(emb, x, ain);

    // 2) persistent attention chain; final epilogue writes hplus
    attn_chain<<<HDIM / 16, 256>>>(feature, attention, map_W, map_b, ai_W, ai_b,
                                   ah_W, ah_b, ao_W, ao_b, buf0, buf1,
                                   hiddens, hplus);

    // 3) all 8 gh GEMMs via TMA (192 CTAs)
    gemm_tma<<<dim3(3 * HDIM / 128, NLAYER), 256, SM_TMA>>>(
        mA_gh, mW_gh, gru_bhh, gh, 3 * HDIM, 3 * HDIM);

    // 4) barrier-free persistent GRU chain (128 CTAs)
    gru_chain<<<128, 384, SM_CH>>>(mA_ch, mW_ch, ain, nh, h1,
                                   gru_bih, gh, hplus);

    // 5) output projection via TMA (250 CTAs) + log-softmax
    gemm_tma<<<dim3(VDIM / 128, 1), 256, SM_TMA>>>(
        mA_out, mW_out, out_b, logp, VDIM, 0);
    log_softmax_kernel<<<BATCH, 1024>>>(logp);
}

// round 13
// speedup vs baseline: 1.3500x; 1.3500x over previous
#include <cuda_runtime.h>
#include <cuda.h>
#include <math.h>
#include <stdint.h>

#define BATCH 64
#define EDIM 1024
#define HDIM 1024
#define FDIM 2048
#define VDIM 32000
#define NLAYER 8
#define BH (BATCH * HDIM)

// ---------------- scratch (no allocation allowed) ----------------
__device__ __align__(16) float g_ain[NLAYER * BATCH * EDIM];
__device__ __align__(16) float g_buf0[BATCH * HDIM];
__device__ __align__(16) float g_buf1[BATCH * HDIM];
__device__ __align__(16) float g_gh[NLAYER * BATCH * 3 * HDIM];
__device__ __align__(16) float g_hplus[NLAYER * BATCH * HDIM];
__device__ int g_bar[NLAYER];
__device__ int g_bar2[4];

// ---------------- ptx helpers ----------------
__device__ __forceinline__ uint32_t tfb(float x) { return __float_as_uint(x); }

__device__ __forceinline__ void cp16(uint32_t saddr, const void* g) {
    asm volatile("cp.async.cg.shared.global [%0], [%1], 16;\n" ::"r"(saddr), "l"(g));
}
__device__ __forceinline__ void cp_commit() { asm volatile("cp.async.commit_group;\n"); }
template <int N>
__device__ __forceinline__ void cp_wait() { asm volatile("cp.async.wait_group %0;\n" ::"n"(N)); }

__device__ __forceinline__ void mbar_init(uint32_t mbar, uint32_t cnt) {
    asm volatile("mbarrier.init.shared.b64 [%0], %1;" ::"r"(mbar), "r"(cnt) : "memory");
}
__device__ __forceinline__ void mbar_expect(uint32_t mbar, uint32_t bytes) {
    asm volatile("mbarrier.arrive.expect_tx.shared.b64 _, [%0], %1;"
                 ::"r"(mbar), "r"(bytes) : "memory");
}
__device__ __forceinline__ void mbar_arrive(uint32_t mbar) {
    asm volatile("mbarrier.arrive.shared.b64 _, [%0];" ::"r"(mbar) : "memory");
}
__device__ __forceinline__ void mbar_wait(uint32_t mbar, uint32_t parity) {
    asm volatile(
        "{\n\t.reg .pred P;\n"
        "LW_%=:\n\t"
        "mbarrier.try_wait.parity.acquire.cta.shared::cta.b64 P, [%0], %1, 0x989680;\n\t"
        "@P bra LD_%=;\n\t"
        "bra LW_%=;\n"
        "LD_%=:\n\t}"
        ::"r"(mbar), "r"(parity) : "memory");
}
__device__ __forceinline__ void tma3(uint32_t dst, const CUtensorMap* map,
                                     int x, int y, int z, uint32_t mbar) {
    asm volatile(
        "cp.async.bulk.tensor.3d.shared::cta.global.tile.mbarrier::complete_tx::bytes "
        "[%0], [%1, {%2, %3, %4}], [%5];"
        ::"r"(dst), "l"(map), "r"(x), "r"(y), "r"(z), "r"(mbar) : "memory");
}
__device__ __forceinline__ void tma4(uint32_t dst, const CUtensorMap* map,
                                     int x, int y, int z, int w, uint32_t mbar) {
    asm volatile(
        "cp.async.bulk.tensor.4d.shared::cta.global.tile.mbarrier::complete_tx::bytes "
        "[%0], [%1, {%2, %3, %4, %5}], [%6];"
        ::"r"(dst), "l"(map), "r"(x), "r"(y), "r"(z), "r"(w), "r"(mbar) : "memory");
}
__device__ __forceinline__ void fence_async() {
    asm volatile("fence.proxy.async;" ::: "memory");
}

__device__ __forceinline__ void mma8(float* c, uint32_t a0, uint32_t a1, uint32_t a2,
                                     uint32_t a3, uint32_t b0, uint32_t b1) {
    asm volatile(
        "mma.sync.aligned.m16n8k8.row.col.f32.tf32.tf32.f32 "
        "{%0,%1,%2,%3}, {%4,%5,%6,%7}, {%8,%9}, {%0,%1,%2,%3};\n"
        : "+f"(c[0]), "+f"(c[1]), "+f"(c[2]), "+f"(c[3])
        : "r"(a0), "r"(a1), "r"(a2), "r"(a3), "r"(b0), "r"(b1));
}

// ---------------- embed (into ain[0]) + barrier init ----------------
__global__ void embed_relu_kernel(const float* __restrict__ emb,
                                  const int* __restrict__ x,
                                  float* __restrict__ ain0) {
    if (blockIdx.x == 0) {
        const int t = threadIdx.x;
        if (t < NLAYER) g_bar[t] = 0;
        else if (t < NLAYER + 4) g_bar2[t - NLAYER] = 0;
    }
    const int b = blockIdx.x;
    const int row = x[b];
    const float* src = emb + (size_t)row * EDIM;
    float* dst = ain0 + (size_t)b * EDIM;
    for (int e = threadIdx.x; e < EDIM; e += blockDim.x) {
        float v = src[e];
        dst[e] = v > 0.f ? v : 0.f;
    }
}

// ---------------- persistent attention chain (cp.async, 64 blocks) ----------------
__global__ __launch_bounds__(256) void attn_chain(
    const float* __restrict__ feature, const float* __restrict__ attention,
    const float* __restrict__ mapW, const float* __restrict__ mapb,
    const float* __restrict__ aiW, const float* __restrict__ aib,
    const float* __restrict__ ahW, const float* __restrict__ ahb,
    const float* __restrict__ aoW, const float* __restrict__ aob,
    float* __restrict__ buf0, float* __restrict__ buf1,
    const float* __restrict__ hiddens, float* __restrict__ hplus) {
    constexpr int S = 3, LDT = 36, BN = 16;
    __shared__ float As[S * 64 * LDT];
    __shared__ float Ws[S * BN * LDT];

    const float* Aptr[4] = {feature, buf0, buf1, buf0};
    const float* Wptr[4] = {mapW, aiW, ahW, aoW};
    const float* bptr[4] = {mapb, aib, ahb, aob};
    float* optr[3] = {buf0, buf1, buf0};
    const int Ks[4] = {FDIM, HDIM, HDIM, HDIM};

    const int tid = threadIdx.x, lane = tid & 31, warp = tid >> 5;
    const int wm = warp & 3, wn = warp >> 2;
    const int r = lane >> 2, kk = lane & 3;
    const int nBlock = blockIdx.x * BN;

    const uint32_t sA = (uint32_t)__cvta_generic_to_shared(As);
    const uint32_t sW = (uint32_t)__cvta_generic_to_shared(Ws);

    for (int layer = 0; layer < 4; layer++) {
        const float* A = Aptr[layer];
        const float* W = Wptr[layer];
        const int K = Ks[layer];
        const int nK = K / 32;

        auto issue = [&](int st, int k0) {
#pragma unroll
            for (int t = 0; t < 2; t++) {
                const int idx = tid + t * 256;
                const int m = idx >> 3, k4 = idx & 7;
                cp16(sA + (uint32_t)(((st * 64 + m) * LDT + k4 * 4) * 4),
                     A + (size_t)m * K + k0 + k4 * 4);
            }
            if (tid < BN * 8) {
                const int wr = tid >> 3, k4 = tid & 7;
                cp16(sW + (uint32_t)(((st * BN + wr) * LDT + k4 * 4) * 4),
                     W + (size_t)(nBlock + wr) * K + k0 + k4 * 4);
            }
        };

#pragma unroll
        for (int p = 0; p < S - 1; p++) {
            if (p < nK) issue(p, p * 32);
            cp_commit();
        }

        float acc[4] = {0.f, 0.f, 0.f, 0.f};
        for (int kt = 0; kt < nK; kt++) {
            cp_wait<S - 2>();
            __syncthreads();
            const int pf = kt + S - 1;
            if (pf < nK) issue(pf % S, pf * 32);
            cp_commit();
            const float* a_ = As + (kt % S) * 64 * LDT;
            const float* w_ = Ws + (kt % S) * BN * LDT;
#pragma unroll
            for (int s = 0; s < 4; s++) {
                const int col = s * 8 + kk;
                const uint32_t a0 = tfb(a_[(wm * 16 + r) * LDT + col]);
                const uint32_t a1 = tfb(a_[(wm * 16 + r + 8) * LDT + col]);
                const uint32_t a2 = tfb(a_[(wm * 16 + r) * LDT + col + 4]);
                const uint32_t a3 = tfb(a_[(wm * 16 + r + 8) * LDT + col + 4]);
                const int n = wn * 8 + r;
                mma8(acc, a0, a1, a2, a3, tfb(w_[n * LDT + col]),
                     tfb(w_[n * LDT + col + 4]));
            }
        }
        cp_wait<0>();

        const int row0 = wm * 16 + r;
        const int col = nBlock + wn * 8 + 2 * kk;
        const float b0v = bptr[layer][col], b1v = bptr[layer][col + 1];
        float v0 = fmaxf(acc[0] + b0v, 0.f), v1 = fmaxf(acc[1] + b1v, 0.f);
        float v2 = fmaxf(acc[2] + b0v, 0.f), v3 = fmaxf(acc[3] + b1v, 0.f);
        if (layer == 0) {
            v0 += attention[(size_t)row0 * HDIM + col];
            v1 += attention[(size_t)row0 * HDIM + col + 1];
            v2 += attention[(size_t)(row0 + 8) * HDIM + col];
            v3 += attention[(size_t)(row0 + 8) * HDIM + col + 1];
        }
        if (layer < 3) {
            float* o = optr[layer];
            *reinterpret_cast<float2*>(o + (size_t)row0 * HDIM + col) = make_float2(v0, v1);
            *reinterpret_cast<float2*>(o + (size_t)(row0 + 8) * HDIM + col) = make_float2(v2, v3);
        } else {
#pragma unroll
            for (int l = 0; l < NLAYER; l++) {
                const size_t b0i = (size_t)l * BH + (size_t)row0 * HDIM + col;
                const size_t b1i = (size_t)l * BH + (size_t)(row0 + 8) * HDIM + col;
                float2 h0 = *reinterpret_cast<const float2*>(hiddens + b0i);
                float2 h8 = *reinterpret_cast<const float2*>(hiddens + b1i);
                *reinterpret_cast<float2*>(hplus + b0i) = make_float2(h0.x + v0, h0.y + v1);
                *reinterpret_cast<float2*>(hplus + b1i) = make_float2(h8.x + v2, h8.y + v3);
            }
            fence_async();
        }

        if (layer < 3) {
            __threadfence();
            __syncthreads();
            if (tid == 0) {
                atomicAdd(&g_bar2[layer], 1);
                while (atomicAdd(&g_bar2[layer], 0) < (int)gridDim.x) __nanosleep(32);
            }
            __syncthreads();
        }
    }
}

// ---------------- TMA tensormap GEMM: C[64,N] = A @ W^T + bias (BN=128, K=1024) -----
__global__ __launch_bounds__(256) void gemm_tma(
    const __grid_constant__ CUtensorMap mapA,
    const __grid_constant__ CUtensorMap mapW,
    const float* __restrict__ bias, float* __restrict__ out,
    int N, int biasStride) {
    constexpr int BN = 128;
    constexpr int STG = (64 + BN) * 32 * 4;
    extern __shared__ float sm[];
    const uint32_t sb = (uint32_t)__cvta_generic_to_shared(sm);
    const uint32_t tiles = sb + 1024;

    const int tid = threadIdx.x, lane = tid & 31, warp = tid >> 5;
    const int wm = warp & 3, wn = warp >> 2;
    const int r = lane >> 2, kk = lane & 3;
    const int nBlock = blockIdx.x * BN;
    const int layer = blockIdx.y;

    bias += (size_t)layer * biasStride;
    out += (size_t)layer * BATCH * N;

    if (tid == 0) {
#pragma unroll
        for (int s = 0; s < 4; s++) mbar_init(sb + s * 8, 1);
    }
    __syncthreads();

    auto fill = [&](int s, int kt) {
        if (tid == 0) {
            const uint32_t mb = sb + s * 8;
            mbar_expect(mb, STG);
            const uint32_t dA = tiles + s * STG;
            tma3(dA, &mapA, kt * 32, 0, layer, mb);
            tma3(dA + 64 * 128, &mapW, kt * 32, nBlock, layer, mb);
        }
    };
    fill(0, 0); fill(1, 1); fill(2, 2);

    float acc[8][4];
#pragma unroll
    for (int i = 0; i < 8; i++)
#pragma unroll
        for (int j = 0; j < 4; j++) acc[i][j] = 0.f;

    const int swz = r << 2;
    for (int kt = 0; kt < 32; kt++) {
        if (kt + 3 < 32) fill((kt + 3) & 3, kt + 3);
        const int s = kt & 3;
        mbar_wait(sb + s * 8, (kt >> 2) & 1);
        const float* a_ = sm + 256 + s * (STG / 4);
        const float* w_ = a_ + 64 * 32;
#pragma unroll
        for (int q = 0; q < 4; q++) {
            const int col = (q * 8 + kk) ^ swz;
            const int col4 = col ^ 4;
            const int m0 = wm * 16 + r;
            const uint32_t a0 = tfb(a_[m0 * 32 + col]);
            const uint32_t a1 = tfb(a_[(m0 + 8) * 32 + col]);
            const uint32_t a2 = tfb(a_[m0 * 32 + col4]);
            const uint32_t a3 = tfb(a_[(m0 + 8) * 32 + col4]);
#pragma unroll
            for (int nt = 0; nt < 8; nt++) {
                const int n = wn * 64 + nt * 8 + r;
                mma8(acc[nt], a0, a1, a2, a3, tfb(w_[n * 32 + col]),
                     tfb(w_[n * 32 + col4]));
            }
        }
        __syncthreads();
    }

    const int row0 = wm * 16 + r;
#pragma unroll
    for (int nt = 0; nt < 8; nt++) {
        const int col = nBlock + wn * 64 + nt * 8 + 2 * kk;
        const float b0v = bias[col], b1v = bias[col + 1];
        *reinterpret_cast<float2*>(out + (size_t)row0 * N + col) =
            make_float2(acc[nt][0] + b0v, acc[nt][1] + b1v);
        *reinterpret_cast<float2*>(out + (size_t)(row0 + 8) * N + col) =
            make_float2(acc[nt][2] + b0v, acc[nt][3] + b1v);
    }
}

// ---------------- persistent fused GRU chain v8 ----------------
// 128 CTAs x 8 h-dims, FULL K (no split-K handshake). TMA double-panel stages
// (BK=64), full barrier count=2 (W fill + A fill arrive separately) so W panels
// prefetch across the grid barrier. gh/hplus epilogue operands staged via cp.async.
__global__ __launch_bounds__(384) void gru_chain(
    const __grid_constant__ CUtensorMap mapA,
    const __grid_constant__ CUtensorMap mapW,
    float* __restrict__ ain, float* __restrict__ nh, float* __restrict__ h1,
    const float* __restrict__ gru_bih, const float* __restrict__ gh,
    const float* __restrict__ hplus) {
    constexpr int SLOT = 22528;   // A 16384 + W 6144
    constexpr int CLD = 26;
    extern __shared__ float sm[];
    const uint32_t sb = (uint32_t)__cvta_generic_to_shared(sm);
    const uint32_t tiles = sb + 1024;
    float* Cs = sm + 256 + 4 * (SLOT / 4);       // 64*26
    float* ghs = Cs + 64 * CLD;                  // 64*24
    float* hps = ghs + 64 * 24;                  // 64*8
    const uint32_t sGh = (uint32_t)__cvta_generic_to_shared(ghs);
    const uint32_t sHp = (uint32_t)__cvta_generic_to_shared(hps);

    const int g = blockIdx.x;
    const int h0 = g * 8;
    const int tid = threadIdx.x, lane = tid & 31, warp = tid >> 5;
    const int wm = warp & 3, sec = warp >> 2;    // 12 warps: 4 M x 3 gates
    const int r = lane >> 2, kk = lane & 3;
    const int swz = r << 2;

    if (tid == 0) {
#pragma unroll
        for (int s = 0; s < 4; s++) {
            mbar_init(sb + s * 16, 2);        // full: W fill + A fill
            mbar_init(sb + s * 16 + 8, 12);   // empty: 12 warps
        }
    }
    __syncthreads();

    auto fillW = [&](int gidx) {     // gidx = layer*16 + kt
        const int s = gidx & 3;
        const int n = gidx >> 2;
        if (n > 0) mbar_wait(sb + s * 16 + 8, (n - 1) & 1);
        const uint32_t mb = sb + s * 16;
        mbar_expect(mb, 6144);
        const int layer = gidx >> 4, kt = gidx & 15;
        const int x0 = kt * 64;
        const uint32_t dst = tiles + s * SLOT + 16384;
        tma4(dst, &mapW, x0, h0, 0, layer, mb);
        tma4(dst + 3072, &mapW, x0 + 32, h0, 0, layer, mb);
    };
    auto fillA = [&](int gidx) {
        const int s = gidx & 3;
        const uint32_t mb = sb + s * 16;
        mbar_expect(mb, 16384);
        const int layer = gidx >> 4, kt = gidx & 15;
        const int x0 = kt * 64;
        const uint32_t dst = tiles + s * SLOT;
        tma3(dst, &mapA, x0, 0, layer, mb);
        tma3(dst + 8192, &mapA, x0 + 32, 0, layer, mb);
    };

    if (tid == 0) {
        fillW(0); fillA(0); fillW(1); fillA(1); fillW(2); fillA(2);
    }

    float prev[2];

    for (int layer = 0; layer < NLAYER; layer++) {
        const float* bih = gru_bih + (size_t)layer * 3 * HDIM;
        float* outh = nh + (size_t)layer * BH;
        float* ainN = ain + (size_t)(layer + 1) * BH;
        const int g0 = layer * 16;

        // stage epilogue operands (gh 64x24, hplus 64x8) via cp.async
        {
            const int pair = tid >> 1, half = tid & 1;   // 192 pairs
            if (pair < 192) {
                const int b = pair / 3, gate = pair % 3;
                cp16(sGh + (uint32_t)((b * 24 + gate * 8 + half * 4) * 4),
                     gh + (size_t)layer * BATCH * 3 * HDIM + (size_t)b * 3 * HDIM +
                         gate * HDIM + h0 + half * 4);
            }
            if (tid < 128) {
                const int b = tid >> 1, half = tid & 1;
                cp16(sHp + (uint32_t)((b * 8 + half * 4) * 4),
                     hplus + (size_t)layer * BH + (size_t)b * HDIM + h0 + half * 4);
            }
            cp_commit();
        }

        float acc[4] = {0.f, 0.f, 0.f, 0.f};
        for (int kt = 0; kt < 16; kt++) {
            if (tid == 0 && kt + 3 < 16) { fillW(g0 + kt + 3); fillA(g0 + kt + 3); }
            const int gidx = g0 + kt;
            const int s = gidx & 3;
            mbar_wait(sb + s * 16, (gidx >> 2) & 1);
            const float* stg = sm + 256 + s * (SLOT / 4);
#pragma unroll
            for (int q = 0; q < 8; q++) {
                const int p = q >> 2;
                const float* a_ = stg + p * 2048;
                const float* w_ = stg + 4096 + p * 768;
                const int col = ((q & 3) * 8 + kk) ^ swz;
                const int col4 = col ^ 4;
                const int m0 = wm * 16 + r;
                const uint32_t a0 = tfb(a_[m0 * 32 + col]);
                const uint32_t a1 = tfb(a_[(m0 + 8) * 32 + col]);
                const uint32_t a2 = tfb(a_[m0 * 32 + col4]);
                const uint32_t a3 = tfb(a_[(m0 + 8) * 32 + col4]);
                const int brow = sec * 8 + r;
                mma8(acc, a0, a1, a2, a3, tfb(w_[brow * 32 + col]),
                     tfb(w_[brow * 32 + col4]));
            }
            if (lane == 0) mbar_arrive(sb + s * 16 + 8);
        }

        // prefetch next layer's W panels before the grid barrier
        if (tid == 0 && layer < NLAYER - 1) {
            fillW(g0 + 16); fillW(g0 + 17); fillW(g0 + 18);
        }

        // stash gi tile
        const int row0 = wm * 16 + r;
        const int cl = sec * 8 + 2 * kk;
        *reinterpret_cast<float2*>(&Cs[row0 * CLD + cl]) = make_float2(acc[0], acc[1]);
        *reinterpret_cast<float2*>(&Cs[(row0 + 8) * CLD + cl]) = make_float2(acc[2], acc[3]);
        cp_wait<0>();
        __syncthreads();

        // gate epilogue (smem-resident operands)
        int t = 0;
        for (int idx = tid; idx < 512; idx += 384, t++) {
            const int b = idx >> 3, hh = idx & 7;
            const int h = h0 + hh;
            const float ir = Cs[b * CLD + hh] + bih[h];
            const float iz = Cs[b * CLD + 8 + hh] + bih[HDIM + h];
            const float in_ = Cs[b * CLD + 16 + hh] + bih[2 * HDIM + h];
            const float rr = 1.f / (1.f + expf(-(ir + ghs[b * 24 + hh])));
            const float zz = 1.f / (1.f + expf(-(iz + ghs[b * 24 + 8 + hh])));
            const float nn = tanhf(in_ + rr * ghs[b * 24 + 16 + hh]);
            const float hp = hps[b * 8 + hh];
            const float o = (1.f - zz) * nn + zz * hp;
            outh[(size_t)b * HDIM + h] = o;
            if (layer == 0) h1[(size_t)b * HDIM + h] = o;
            if (layer < NLAYER - 1) {
                const float nx = (layer < 2) ? o : (o + prev[t]);
                ainN[(size_t)b * HDIM + h] = nx;
            }
            prev[t] = o;
        }

        if (layer < NLAYER - 1) {
            __threadfence();
            fence_async();
            __syncthreads();
            if (tid == 0) {
                atomicAdd(&g_bar[layer], 1);
                while (atomicAdd(&g_bar[layer], 0) < (int)gridDim.x) __nanosleep(32);
                // A fills for next layer's prologue stages (W already issued)
                fillA(g0 + 16); fillA(g0 + 17); fillA(g0 + 18);
            }
            __syncthreads();
        }
    }
}

// ---------------- 2-pass online log_softmax ----------------
__global__ __launch_bounds__(1024) void log_softmax_kernel(float* __restrict__ logits) {
    const int b = blockIdx.x;
    float* row = logits + (size_t)b * VDIM;
    __shared__ float smax[32], ssum[32];
    __shared__ float s_lse;
    const int lane = threadIdx.x & 31;
    const int wid = threadIdx.x >> 5;

    float m = -1e30f, s = 0.f;
    const float4* r4 = reinterpret_cast<const float4*>(row);
    for (int v = threadIdx.x; v < VDIM / 4; v += blockDim.x) {
        float4 x = r4[v];
#define ONE(val) { float d = (val) - m; \
        if (d > 0.f) { s = s * __expf(-d) + 1.f; m = (val); } else s += __expf(d); }
        ONE(x.x) ONE(x.y) ONE(x.z) ONE(x.w)
#undef ONE
    }
#pragma unroll
    for (int o = 16; o; o >>= 1) {
        float mo = __shfl_xor_sync(0xffffffffu, m, o);
        float so = __shfl_xor_sync(0xffffffffu, s, o);
        float mn = fmaxf(m, mo);
        s = s * __expf(m - mn) + so * __expf(mo - mn);
        m = mn;
    }
    if (lane == 0) { smax[wid] = m; ssum[wid] = s; }
    __syncthreads();
    if (wid == 0) {
        float mm = (lane < (blockDim.x >> 5)) ? smax[lane] : -1e30f;
        float ss = (lane < (blockDim.x >> 5)) ? ssum[lane] : 0.f;
#pragma unroll
        for (int o = 16; o; o >>= 1) {
            float mo = __shfl_xor_sync(0xffffffffu, mm, o);
            float so = __shfl_xor_sync(0xffffffffu, ss, o);
            float mn = fmaxf(mm, mo);
            ss = ss * __expf(mm - mn) + so * __expf(mo - mn);
            mm = mn;
        }
        if (lane == 0) s_lse = mm + logf(ss);
    }
    __syncthreads();
    const float lse = s_lse;
    float4* w4 = reinterpret_cast<float4*>(row);
    for (int v = threadIdx.x; v < VDIM / 4; v += blockDim.x) {
        float4 x = w4[v];
        x.x -= lse; x.y -= lse; x.z -= lse; x.w -= lse;
        w4[v] = x;
    }
}

// ---------------- host-side tensormap encoding ----------------
typedef CUresult (CUDAAPI* EncFn)(
    CUtensorMap*, CUtensorMapDataType, cuuint32_t, void*,
    const cuuint64_t*, const cuuint64_t*, const cuuint32_t*, const cuuint32_t*,
    CUtensorMapInterleave, CUtensorMapSwizzle, CUtensorMapL2promotion,
    CUtensorMapFloatOOBfill);

static void make_map3(EncFn enc, CUtensorMap* m, const void* p,
                      unsigned long long d0, unsigned long long d1,
                      unsigned long long d2, unsigned int b1) {
    cuuint64_t dims[3] = {d0, d1, d2};
    cuuint64_t strides[2] = {d0 * 4, d0 * d1 * 4};
    cuuint32_t box[3] = {32, b1, 1};
    cuuint32_t es[3] = {1, 1, 1};
    enc(m, CU_TENSOR_MAP_DATA_TYPE_FLOAT32, 3, (void*)p, dims, strides, box, es,
        CU_TENSOR_MAP_INTERLEAVE_NONE, CU_TENSOR_MAP_SWIZZLE_128B,
        CU_TENSOR_MAP_L2_PROMOTION_L2_128B, CU_TENSOR_MAP_FLOAT_OOB_FILL_NONE);
}

static void make_map4_wih(EncFn enc, CUtensorMap* m, const void* p) {
    cuuint64_t dims[4] = {EDIM, HDIM, 3, NLAYER};
    cuuint64_t strides[3] = {(cuuint64_t)EDIM * 4,
                             (cuuint64_t)HDIM * EDIM * 4,
                             (cuuint64_t)3 * HDIM * EDIM * 4};
    cuuint32_t box[4] = {32, 8, 3, 1};
    cuuint32_t es[4] = {1, 1, 1, 1};
    enc(m, CU_TENSOR_MAP_DATA_TYPE_FLOAT32, 4, (void*)p, dims, strides, box, es,
        CU_TENSOR_MAP_INTERLEAVE_NONE, CU_TENSOR_MAP_SWIZZLE_128B,
        CU_TENSOR_MAP_L2_PROMOTION_L2_128B, CU_TENSOR_MAP_FLOAT_OOB_FILL_NONE);
}

// ---------------- launch ----------------
extern "C" void kernel_launch(void* const* d_in, const int* in_sizes, int n_in,
                              void* d_out, int out_size) {
    const float* feature   = (const float*)d_in[0];
    const int*   x         = (const int*)d_in[1];
    const float* attention = (const float*)d_in[2];
    const float* hiddens   = (const float*)d_in[3];
    const float* emb       = (const float*)d_in[4];
    const float* map_W     = (const float*)d_in[5];
    const float* map_b     = (const float*)d_in[6];
    const float* ai_W      = (const float*)d_in[7];
    const float* ai_b      = (const float*)d_in[8];
    const float* ah_W      = (const float*)d_in[9];
    const float* ah_b      = (const float*)d_in[10];
    const float* ao_W      = (const float*)d_in[11];
    const float* ao_b      = (const float*)d_in[12];
    const float* gru_Wih   = (const float*)d_in[13];
    const float* gru_Whh   = (const float*)d_in[14];
    const float* gru_bih   = (const float*)d_in[15];
    const float* gru_bhh   = (const float*)d_in[16];
    const float* out_W     = (const float*)d_in[17];
    const float* out_b     = (const float*)d_in[18];

    float* out = (float*)d_out;
    float* logp = out;
    float* h1   = out + (size_t)BATCH * VDIM;
    float* nh   = h1 + (size_t)BATCH * HDIM;

    float *ain, *buf0, *buf1, *gh, *hplus;
    cudaGetSymbolAddress((void**)&ain, g_ain);
    cudaGetSymbolAddress((void**)&buf0, g_buf0);
    cudaGetSymbolAddress((void**)&buf1, g_buf1);
    cudaGetSymbolAddress((void**)&gh, g_gh);
    cudaGetSymbolAddress((void**)&hplus, g_hplus);

    EncFn enc = nullptr;
    cudaDriverEntryPointQueryResult qr;
    cudaGetDriverEntryPoint("cuTensorMapEncodeTiled", (void**)&enc,
                            cudaEnableDefault, &qr);
    CUtensorMap mW_gh, mA_gh, mW_out, mA_out, mA_ch, mW_ch;
    make_map3(enc, &mW_gh, gru_Whh, HDIM, 3 * HDIM, NLAYER, 128);
    make_map3(enc, &mA_gh, hplus, HDIM, BATCH, NLAYER, 64);
    make_map3(enc, &mW_out, out_W, HDIM, VDIM, 1, 128);
    make_map3(enc, &mA_out, nh + 7 * (size_t)BH, HDIM, BATCH, 1, 64);
    make_map3(enc, &mA_ch, ain, EDIM, BATCH, NLAYER, 64);
    make_map4_wih(enc, &mW_ch, gru_Wih);

    const int SM_TMA = 1024 + 4 * (64 + 128) * 32 * 4;                        // 99328
    const int SM_CH  = 1024 + 4 * 22528 + (64 * 26 + 64 * 24 + 64 * 8) * 4;  // 105984
    cudaFuncSetAttribute((const void*)gemm_tma,
                         cudaFuncAttributeMaxDynamicSharedMemorySize, SM_TMA);
    cudaFuncSetAttribute((const void*)gru_chain,
                         cudaFuncAttributeMaxDynamicSharedMemorySize, SM_CH);

    // 1) embed into ain[0] (+ barrier init)
    embed_relu_kernel<<<BATCH, 256>>>(emb, x, ain);

    // 2) persistent attention chain; final epilogue writes hplus
    attn_chain<<<HDIM / 16, 256>>>(feature, attention, map_W, map_b, ai_W, ai_b,
                                   ah_W, ah_b, ao_W, ao_b, buf0, buf1,
                                   hiddens, hplus);

    // 3) all 8 gh GEMMs via TMA (192 CTAs)
    gemm_tma<<<dim3(3 * HDIM / 128, NLAYER), 256, SM_TMA>>>(
        mA_gh, mW_gh, gru_bhh, gh, 3 * HDIM, 3 * HDIM);

    // 4) persistent GRU chain, full-K per CTA (128 CTAs x 8 h-dims)
    gru_chain<<<128, 384, SM_CH>>>(mA_ch, mW_ch, ain, nh, h1,
                                   gru_bih, gh, hplus);

    // 5) output projection via TMA (250 CTAs) + log-softmax
    gemm_tma<<<dim3(VDIM / 128, 1), 256, SM_TMA>>>(
        mA_out, mW_out, out_b, logp, VDIM, 0);
    log_softmax_kernel<<<BATCH, 1024>>>(logp);
}

// round 14
// speedup vs baseline: 1.4738x; 1.0917x over previous
#include <cuda_runtime.h>
#include <cuda.h>
#include <math.h>
#include <stdint.h>

#define BATCH 64
#define EDIM 1024
#define HDIM 1024
#define FDIM 2048
#define VDIM 32000
#define NLAYER 8
#define BH (BATCH * HDIM)

// ---------------- scratch (no allocation allowed) ----------------
__device__ __align__(16) float g_ain[NLAYER * BATCH * EDIM];
__device__ __align__(16) float g_buf0[BATCH * HDIM];
__device__ __align__(16) float g_buf1[BATCH * HDIM];
__device__ __align__(16) float g_gh[NLAYER * BATCH * 3 * HDIM];
__device__ __align__(16) float g_hplus[NLAYER * BATCH * HDIM];
__device__ int g_bar[NLAYER];
__device__ int g_bar2[4];

// ---------------- ptx helpers ----------------
__device__ __forceinline__ uint32_t tfb(float x) { return __float_as_uint(x); }

__device__ __forceinline__ void cp16(uint32_t saddr, const void* g) {
    asm volatile("cp.async.cg.shared.global [%0], [%1], 16;\n" ::"r"(saddr), "l"(g));
}
__device__ __forceinline__ void cp_commit() { asm volatile("cp.async.commit_group;\n"); }
template <int N>
__device__ __forceinline__ void cp_wait() { asm volatile("cp.async.wait_group %0;\n" ::"n"(N)); }

__device__ __forceinline__ void mbar_init(uint32_t mbar, uint32_t cnt) {
    asm volatile("mbarrier.init.shared.b64 [%0], %1;" ::"r"(mbar), "r"(cnt) : "memory");
}
__device__ __forceinline__ void mbar_expect(uint32_t mbar, uint32_t bytes) {
    asm volatile("mbarrier.arrive.expect_tx.shared.b64 _, [%0], %1;"
                 ::"r"(mbar), "r"(bytes) : "memory");
}
__device__ __forceinline__ void mbar_arrive(uint32_t mbar) {
    asm volatile("mbarrier.arrive.shared.b64 _, [%0];" ::"r"(mbar) : "memory");
}
__device__ __forceinline__ void mbar_wait(uint32_t mbar, uint32_t parity) {
    asm volatile(
        "{\n\t.reg .pred P;\n"
        "LW_%=:\n\t"
        "mbarrier.try_wait.parity.acquire.cta.shared::cta.b64 P, [%0], %1, 0x989680;\n\t"
        "@P bra LD_%=;\n\t"
        "bra LW_%=;\n"
        "LD_%=:\n\t}"
        ::"r"(mbar), "r"(parity) : "memory");
}
__device__ __forceinline__ void tma3(uint32_t dst, const CUtensorMap* map,
                                     int x, int y, int z, uint32_t mbar) {
    asm volatile(
        "cp.async.bulk.tensor.3d.shared::cta.global.tile.mbarrier::complete_tx::bytes "
        "[%0], [%1, {%2, %3, %4}], [%5];"
        ::"r"(dst), "l"(map), "r"(x), "r"(y), "r"(z), "r"(mbar) : "memory");
}
__device__ __forceinline__ void tma4(uint32_t dst, const CUtensorMap* map,
                                     int x, int y, int z, int w, uint32_t mbar) {
    asm volatile(
        "cp.async.bulk.tensor.4d.shared::cta.global.tile.mbarrier::complete_tx::bytes "
        "[%0], [%1, {%2, %3, %4, %5}], [%6];"
        ::"r"(dst), "l"(map), "r"(x), "r"(y), "r"(z), "r"(w), "r"(mbar) : "memory");
}
__device__ __forceinline__ void fence_async() {
    asm volatile("fence.proxy.async;" ::: "memory");
}

__device__ __forceinline__ void mma8(float* c, uint32_t a0, uint32_t a1, uint32_t a2,
                                     uint32_t a3, uint32_t b0, uint32_t b1) {
    asm volatile(
        "mma.sync.aligned.m16n8k8.row.col.f32.tf32.tf32.f32 "
        "{%0,%1,%2,%3}, {%4,%5,%6,%7}, {%8,%9}, {%0,%1,%2,%3};\n"
        : "+f"(c[0]), "+f"(c[1]), "+f"(c[2]), "+f"(c[3])
        : "r"(a0), "r"(a1), "r"(a2), "r"(a3), "r"(b0), "r"(b1));
}

// ---------------- embed (into ain[0]) + barrier init ----------------
__global__ void embed_relu_kernel(const float* __restrict__ emb,
                                  const int* __restrict__ x,
                                  float* __restrict__ ain0) {
    if (blockIdx.x == 0) {
        const int t = threadIdx.x;
        if (t < NLAYER) g_bar[t] = 0;
        else if (t < NLAYER + 4) g_bar2[t - NLAYER] = 0;
    }
    const int b = blockIdx.x;
    const int row = x[b];
    const float* src = emb + (size_t)row * EDIM;
    float* dst = ain0 + (size_t)b * EDIM;
    for (int e = threadIdx.x; e < EDIM; e += blockDim.x) {
        float v = src[e];
        dst[e] = v > 0.f ? v : 0.f;
    }
}

// ---------------- persistent attention chain (cp.async, 64 blocks) ----------------
__global__ __launch_bounds__(256) void attn_chain(
    const float* __restrict__ feature, const float* __restrict__ attention,
    const float* __restrict__ mapW, const float* __restrict__ mapb,
    const float* __restrict__ aiW, const float* __restrict__ aib,
    const float* __restrict__ ahW, const float* __restrict__ ahb,
    const float* __restrict__ aoW, const float* __restrict__ aob,
    float* __restrict__ buf0, float* __restrict__ buf1,
    const float* __restrict__ hiddens, float* __restrict__ hplus) {
    constexpr int S = 3, LDT = 36, BN = 16;
    __shared__ float As[S * 64 * LDT];
    __shared__ float Ws[S * BN * LDT];

    const float* Aptr[4] = {feature, buf0, buf1, buf0};
    const float* Wptr[4] = {mapW, aiW, ahW, aoW};
    const float* bptr[4] = {mapb, aib, ahb, aob};
    float* optr[3] = {buf0, buf1, buf0};
    const int Ks[4] = {FDIM, HDIM, HDIM, HDIM};

    const int tid = threadIdx.x, lane = tid & 31, warp = tid >> 5;
    const int wm = warp & 3, wn = warp >> 2;
    const int r = lane >> 2, kk = lane & 3;
    const int nBlock = blockIdx.x * BN;

    const uint32_t sA = (uint32_t)__cvta_generic_to_shared(As);
    const uint32_t sW = (uint32_t)__cvta_generic_to_shared(Ws);

    for (int layer = 0; layer < 4; layer++) {
        const float* A = Aptr[layer];
        const float* W = Wptr[layer];
        const int K = Ks[layer];
        const int nK = K / 32;

        auto issue = [&](int st, int k0) {
#pragma unroll
            for (int t = 0; t < 2; t++) {
                const int idx = tid + t * 256;
                const int m = idx >> 3, k4 = idx & 7;
                cp16(sA + (uint32_t)(((st * 64 + m) * LDT + k4 * 4) * 4),
                     A + (size_t)m * K + k0 + k4 * 4);
            }
            if (tid < BN * 8) {
                const int wr = tid >> 3, k4 = tid & 7;
                cp16(sW + (uint32_t)(((st * BN + wr) * LDT + k4 * 4) * 4),
                     W + (size_t)(nBlock + wr) * K + k0 + k4 * 4);
            }
        };

#pragma unroll
        for (int p = 0; p < S - 1; p++) {
            if (p < nK) issue(p, p * 32);
            cp_commit();
        }

        float acc[4] = {0.f, 0.f, 0.f, 0.f};
        for (int kt = 0; kt < nK; kt++) {
            cp_wait<S - 2>();
            __syncthreads();
            const int pf = kt + S - 1;
            if (pf < nK) issue(pf % S, pf * 32);
            cp_commit();
            const float* a_ = As + (kt % S) * 64 * LDT;
            const float* w_ = Ws + (kt % S) * BN * LDT;
#pragma unroll
            for (int s = 0; s < 4; s++) {
                const int col = s * 8 + kk;
                const uint32_t a0 = tfb(a_[(wm * 16 + r) * LDT + col]);
                const uint32_t a1 = tfb(a_[(wm * 16 + r + 8) * LDT + col]);
                const uint32_t a2 = tfb(a_[(wm * 16 + r) * LDT + col + 4]);
                const uint32_t a3 = tfb(a_[(wm * 16 + r + 8) * LDT + col + 4]);
                const int n = wn * 8 + r;
                mma8(acc, a0, a1, a2, a3, tfb(w_[n * LDT + col]),
                     tfb(w_[n * LDT + col + 4]));
            }
        }
        cp_wait<0>();

        const int row0 = wm * 16 + r;
        const int col = nBlock + wn * 8 + 2 * kk;
        const float b0v = bptr[layer][col], b1v = bptr[layer][col + 1];
        float v0 = fmaxf(acc[0] + b0v, 0.f), v1 = fmaxf(acc[1] + b1v, 0.f);
        float v2 = fmaxf(acc[2] + b0v, 0.f), v3 = fmaxf(acc[3] + b1v, 0.f);
        if (layer == 0) {
            v0 += attention[(size_t)row0 * HDIM + col];
            v1 += attention[(size_t)row0 * HDIM + col + 1];
            v2 += attention[(size_t)(row0 + 8) * HDIM + col];
            v3 += attention[(size_t)(row0 + 8) * HDIM + col + 1];
        }
        if (layer < 3) {
            float* o = optr[layer];
            *reinterpret_cast<float2*>(o + (size_t)row0 * HDIM + col) = make_float2(v0, v1);
            *reinterpret_cast<float2*>(o + (size_t)(row0 + 8) * HDIM + col) = make_float2(v2, v3);
        } else {
#pragma unroll
            for (int l = 0; l < NLAYER; l++) {
                const size_t b0i = (size_t)l * BH + (size_t)row0 * HDIM + col;
                const size_t b1i = (size_t)l * BH + (size_t)(row0 + 8) * HDIM + col;
                float2 h0 = *reinterpret_cast<const float2*>(hiddens + b0i);
                float2 h8 = *reinterpret_cast<const float2*>(hiddens + b1i);
                *reinterpret_cast<float2*>(hplus + b0i) = make_float2(h0.x + v0, h0.y + v1);
                *reinterpret_cast<float2*>(hplus + b1i) = make_float2(h8.x + v2, h8.y + v3);
            }
            fence_async();
        }

        if (layer < 3) {
            __threadfence();
            __syncthreads();
            if (tid == 0) {
                atomicAdd(&g_bar2[layer], 1);
                while (atomicAdd(&g_bar2[layer], 0) < (int)gridDim.x) __nanosleep(32);
            }
            __syncthreads();
        }
    }
}

// ---------------- TMA tensormap GEMM: C[64,N] = A @ W^T + bias (BN=128, K=1024) -----
__global__ __launch_bounds__(256) void gemm_tma(
    const __grid_constant__ CUtensorMap mapA,
    const __grid_constant__ CUtensorMap mapW,
    const float* __restrict__ bias, float* __restrict__ out,
    int N, int biasStride) {
    constexpr int BN = 128;
    constexpr int STG = (64 + BN) * 32 * 4;
    extern __shared__ float sm[];
    const uint32_t sb = (uint32_t)__cvta_generic_to_shared(sm);
    const uint32_t tiles = sb + 1024;

    const int tid = threadIdx.x, lane = tid & 31, warp = tid >> 5;
    const int wm = warp & 3, wn = warp >> 2;
    const int r = lane >> 2, kk = lane & 3;
    const int nBlock = blockIdx.x * BN;
    const int layer = blockIdx.y;

    bias += (size_t)layer * biasStride;
    out += (size_t)layer * BATCH * N;

    if (tid == 0) {
#pragma unroll
        for (int s = 0; s < 4; s++) mbar_init(sb + s * 8, 1);
    }
    __syncthreads();

    auto fill = [&](int s, int kt) {
        if (tid == 0) {
            const uint32_t mb = sb + s * 8;
            mbar_expect(mb, STG);
            const uint32_t dA = tiles + s * STG;
            tma3(dA, &mapA, kt * 32, 0, layer, mb);
            tma3(dA + 64 * 128, &mapW, kt * 32, nBlock, layer, mb);
        }
    };
    fill(0, 0); fill(1, 1); fill(2, 2);

    float acc[8][4];
#pragma unroll
    for (int i = 0; i < 8; i++)
#pragma unroll
        for (int j = 0; j < 4; j++) acc[i][j] = 0.f;

    const int swz = r << 2;
    for (int kt = 0; kt < 32; kt++) {
        if (kt + 3 < 32) fill((kt + 3) & 3, kt + 3);
        const int s = kt & 3;
        mbar_wait(sb + s * 8, (kt >> 2) & 1);
        const float* a_ = sm + 256 + s * (STG / 4);
        const float* w_ = a_ + 64 * 32;
#pragma unroll
        for (int q = 0; q < 4; q++) {
            const int col = (q * 8 + kk) ^ swz;
            const int col4 = col ^ 4;
            const int m0 = wm * 16 + r;
            const uint32_t a0 = tfb(a_[m0 * 32 + col]);
            const uint32_t a1 = tfb(a_[(m0 + 8) * 32 + col]);
            const uint32_t a2 = tfb(a_[m0 * 32 + col4]);
            const uint32_t a3 = tfb(a_[(m0 + 8) * 32 + col4]);
#pragma unroll
            for (int nt = 0; nt < 8; nt++) {
                const int n = wn * 64 + nt * 8 + r;
                mma8(acc[nt], a0, a1, a2, a3, tfb(w_[n * 32 + col]),
                     tfb(w_[n * 32 + col4]));
            }
        }
        __syncthreads();
    }

    const int row0 = wm * 16 + r;
#pragma unroll
    for (int nt = 0; nt < 8; nt++) {
        const int col = nBlock + wn * 64 + nt * 8 + 2 * kk;
        const float b0v = bias[col], b1v = bias[col + 1];
        *reinterpret_cast<float2*>(out + (size_t)row0 * N + col) =
            make_float2(acc[nt][0] + b0v, acc[nt][1] + b1v);
        *reinterpret_cast<float2*>(out + (size_t)(row0 + 8) * N + col) =
            make_float2(acc[nt][2] + b0v, acc[nt][3] + b1v);
    }
}

// ---------------- persistent fused GRU chain v9: dedicated producer warp ----------
// 128 CTAs x 8 h-dims, full K. 416 threads = 12 consumer warps + 1 producer warp.
// full[s]: count=2 (W fill + A fill). empty[s]: count=12 (consumer warps).
__global__ __launch_bounds__(416) void gru_chain(
    const __grid_constant__ CUtensorMap mapA,
    const __grid_constant__ CUtensorMap mapW,
    float* __restrict__ ain, float* __restrict__ nh, float* __restrict__ h1,
    const float* __restrict__ gru_bih, const float* __restrict__ gh,
    const float* __restrict__ hplus) {
    constexpr int SLOT = 22528;   // A 16384 + W 6144
    constexpr int CLD = 26;
    extern __shared__ float sm[];
    const uint32_t sb = (uint32_t)__cvta_generic_to_shared(sm);
    const uint32_t tiles = sb + 1024;
    float* Cs = sm + 256 + 4 * (SLOT / 4);       // 64*26
    float* ghs = Cs + 64 * CLD;                  // 64*24
    float* hps = ghs + 64 * 24;                  // 64*8
    const uint32_t sGh = (uint32_t)__cvta_generic_to_shared(ghs);
    const uint32_t sHp = (uint32_t)__cvta_generic_to_shared(hps);

    const int g = blockIdx.x;
    const int h0 = g * 8;
    const int tid = threadIdx.x, lane = tid & 31, warp = tid >> 5;
    const int wm = warp & 3, sec = warp >> 2;    // valid for warps 0-11
    const int r = lane >> 2, kk = lane & 3;
    const int swz = r << 2;
    const bool producer = (warp == 12);

    if (tid == 0) {
#pragma unroll
        for (int s = 0; s < 4; s++) {
            mbar_init(sb + s * 16, 2);        // full: W fill + A fill
            mbar_init(sb + s * 16 + 8, 12);   // empty: 12 consumer warps
        }
    }
    __syncthreads();

    auto fillW = [&](int gidx) {     // gidx = layer*16 + kt
        const int s = gidx & 3;
        const int n = gidx >> 2;
        if (n > 0) mbar_wait(sb + s * 16 + 8, (n - 1) & 1);
        const uint32_t mb = sb + s * 16;
        mbar_expect(mb, 6144);
        const int layer = gidx >> 4, kt = gidx & 15;
        const int x0 = kt * 64;
        const uint32_t dst = tiles + s * SLOT + 16384;
        tma4(dst, &mapW, x0, h0, 0, layer, mb);
        tma4(dst + 3072, &mapW, x0 + 32, h0, 0, layer, mb);
    };
    auto fillA = [&](int gidx) {
        const int s = gidx & 3;
        const uint32_t mb = sb + s * 16;
        mbar_expect(mb, 16384);
        const int layer = gidx >> 4, kt = gidx & 15;
        const int x0 = kt * 64;
        const uint32_t dst = tiles + s * SLOT;
        tma3(dst, &mapA, x0, 0, layer, mb);
        tma3(dst + 8192, &mapA, x0 + 32, 0, layer, mb);
    };

    if (producer && lane == 0) {
        fillW(0); fillA(0); fillW(1); fillA(1); fillW(2); fillA(2);
    }

    float prev[2];

    for (int layer = 0; layer < NLAYER; layer++) {
        const float* bih = gru_bih + (size_t)layer * 3 * HDIM;
        float* outh = nh + (size_t)layer * BH;
        float* ainN = ain + (size_t)(layer + 1) * BH;
        const int g0 = layer * 16;

        // stage epilogue operands (gh 64x24, hplus 64x8) via cp.async
        {
            const int pair = tid >> 1, half = tid & 1;
            if (pair < 192) {
                const int b = pair / 3, gate = pair % 3;
                cp16(sGh + (uint32_t)((b * 24 + gate * 8 + half * 4) * 4),
                     gh + (size_t)layer * BATCH * 3 * HDIM + (size_t)b * 3 * HDIM +
                         gate * HDIM + h0 + half * 4);
            }
            if (tid < 128) {
                const int b = tid >> 1, half = tid & 1;
                cp16(sHp + (uint32_t)((b * 8 + half * 4) * 4),
                     hplus + (size_t)layer * BH + (size_t)b * HDIM + h0 + half * 4);
            }
            cp_commit();
        }

        if (!producer) {
            // -------- consumer warps: pure compute --------
            float acc[4] = {0.f, 0.f, 0.f, 0.f};
            for (int kt = 0; kt < 16; kt++) {
                const int gidx = g0 + kt;
                const int s = gidx & 3;
                mbar_wait(sb + s * 16, (gidx >> 2) & 1);
                const float* stg = sm + 256 + s * (SLOT / 4);
#pragma unroll
                for (int q = 0; q < 8; q++) {
                    const int p = q >> 2;
                    const float* a_ = stg + p * 2048;
                    const float* w_ = stg + 4096 + p * 768;
                    const int col = ((q & 3) * 8 + kk) ^ swz;
                    const int col4 = col ^ 4;
                    const int m0 = wm * 16 + r;
                    const uint32_t a0 = tfb(a_[m0 * 32 + col]);
                    const uint32_t a1 = tfb(a_[(m0 + 8) * 32 + col]);
                    const uint32_t a2 = tfb(a_[m0 * 32 + col4]);
                    const uint32_t a3 = tfb(a_[(m0 + 8) * 32 + col4]);
                    const int brow = sec * 8 + r;
                    mma8(acc, a0, a1, a2, a3, tfb(w_[brow * 32 + col]),
                         tfb(w_[brow * 32 + col4]));
                }
                if (lane == 0) mbar_arrive(sb + s * 16 + 8);
            }
            // stash gi tile
            const int row0 = wm * 16 + r;
            const int cl = sec * 8 + 2 * kk;
            *reinterpret_cast<float2*>(&Cs[row0 * CLD + cl]) =
                make_float2(acc[0], acc[1]);
            *reinterpret_cast<float2*>(&Cs[(row0 + 8) * CLD + cl]) =
                make_float2(acc[2], acc[3]);
        } else if (lane == 0) {
            // -------- producer warp: fills only --------
            for (int kt = 0; kt < 16; kt++) {
                if (layer == 0 && kt < 3) continue;     // prologued
                const int gidx = g0 + kt;
                if (kt < 3) {
                    fillA(gidx);                        // W prefetched last layer
                } else {
                    fillW(gidx); fillA(gidx);
                }
            }
            if (layer < NLAYER - 1) {                   // next layer W prefetch
                fillW(g0 + 16); fillW(g0 + 17); fillW(g0 + 18);
            }
        }

        cp_wait<0>();
        __syncthreads();

        // gate epilogue (smem-resident operands), all 416 threads
        int t = 0;
        for (int idx = tid; idx < 512; idx += 416, t++) {
            const int b = idx >> 3, hh = idx & 7;
            const int h = h0 + hh;
            const float ir = Cs[b * CLD + hh] + bih[h];
            const float iz = Cs[b * CLD + 8 + hh] + bih[HDIM + h];
            const float in_ = Cs[b * CLD + 16 + hh] + bih[2 * HDIM + h];
            const float rr = 1.f / (1.f + expf(-(ir + ghs[b * 24 + hh])));
            const float zz = 1.f / (1.f + expf(-(iz + ghs[b * 24 + 8 + hh])));
            const float nn = tanhf(in_ + rr * ghs[b * 24 + 16 + hh]);
            const float hp = hps[b * 8 + hh];
            const float o = (1.f - zz) * nn + zz * hp;
            outh[(size_t)b * HDIM + h] = o;
            if (layer == 0) h1[(size_t)b * HDIM + h] = o;
            if (layer < NLAYER - 1) {
                const float nx = (layer < 2) ? o : (o + prev[t]);
                ainN[(size_t)b * HDIM + h] = nx;
            }
            prev[t] = o;
        }

        if (layer < NLAYER - 1) {
            __threadfence();
            fence_async();
            __syncthreads();
            if (tid == 0) {
                atomicAdd(&g_bar[layer], 1);
                while (atomicAdd(&g_bar[layer], 0) < (int)gridDim.x) __nanosleep(32);
            }
            __syncthreads();
        }
    }
}

// ---------------- 2-pass online log_softmax ----------------
__global__ __launch_bounds__(1024) void log_softmax_kernel(float* __restrict__ logits) {
    const int b = blockIdx.x;
    float* row = logits + (size_t)b * VDIM;
    __shared__ float smax[32], ssum[32];
    __shared__ float s_lse;
    const int lane = threadIdx.x & 31;
    const int wid = threadIdx.x >> 5;

    float m = -1e30f, s = 0.f;
    const float4* r4 = reinterpret_cast<const float4*>(row);
    for (int v = threadIdx.x; v < VDIM / 4; v += blockDim.x) {
        float4 x = r4[v];
#define ONE(val) { float d = (val) - m; \
        if (d > 0.f) { s = s * __expf(-d) + 1.f; m = (val); } else s += __expf(d); }
        ONE(x.x) ONE(x.y) ONE(x.z) ONE(x.w)
#undef ONE
    }
#pragma unroll
    for (int o = 16; o; o >>= 1) {
        float mo = __shfl_xor_sync(0xffffffffu, m, o);
        float so = __shfl_xor_sync(0xffffffffu, s, o);
        float mn = fmaxf(m, mo);
        s = s * __expf(m - mn) + so * __expf(mo - mn);
        m = mn;
    }
    if (lane == 0) { smax[wid] = m; ssum[wid] = s; }
    __syncthreads();
    if (wid == 0) {
        float mm = (lane < (blockDim.x >> 5)) ? smax[lane] : -1e30f;
        float ss = (lane < (blockDim.x >> 5)) ? ssum[lane] : 0.f;
#pragma unroll
        for (int o = 16; o; o >>= 1) {
            float mo = __shfl_xor_sync(0xffffffffu, mm, o);
            float so = __shfl_xor_sync(0xffffffffu, ss, o);
            float mn = fmaxf(mm, mo);
            ss = ss * __expf(mm - mn) + so * __expf(mo - mn);
            mm = mn;
        }
        if (lane == 0) s_lse = mm + logf(ss);
    }
    __syncthreads();
    const float lse = s_lse;
    float4* w4 = reinterpret_cast<float4*>(row);
    for (int v = threadIdx.x; v < VDIM / 4; v += blockDim.x) {
        float4 x = w4[v];
        x.x -= lse; x.y -= lse; x.z -= lse; x.w -= lse;
        w4[v] = x;
    }
}

// ---------------- host-side tensormap encoding ----------------
typedef CUresult (CUDAAPI* EncFn)(
    CUtensorMap*, CUtensorMapDataType, cuuint32_t, void*,
    const cuuint64_t*, const cuuint64_t*, const cuuint32_t*, const cuuint32_t*,
    CUtensorMapInterleave, CUtensorMapSwizzle, CUtensorMapL2promotion,
    CUtensorMapFloatOOBfill);

static void make_map3(EncFn enc, CUtensorMap* m, const void* p,
                      unsigned long long d0, unsigned long long d1,
                      unsigned long long d2, unsigned int b1) {
    cuuint64_t dims[3] = {d0, d1, d2};
    cuuint64_t strides[2] = {d0 * 4, d0 * d1 * 4};
    cuuint32_t box[3] = {32, b1, 1};
    cuuint32_t es[3] = {1, 1, 1};
    enc(m, CU_TENSOR_MAP_DATA_TYPE_FLOAT32, 3, (void*)p, dims, strides, box, es,
        CU_TENSOR_MAP_INTERLEAVE_NONE, CU_TENSOR_MAP_SWIZZLE_128B,
        CU_TENSOR_MAP_L2_PROMOTION_L2_128B, CU_TENSOR_MAP_FLOAT_OOB_FILL_NONE);
}

static void make_map4_wih(EncFn enc, CUtensorMap* m, const void* p) {
    cuuint64_t dims[4] = {EDIM, HDIM, 3, NLAYER};
    cuuint64_t strides[3] = {(cuuint64_t)EDIM * 4,
                             (cuuint64_t)HDIM * EDIM * 4,
                             (cuuint64_t)3 * HDIM * EDIM * 4};
    cuuint32_t box[4] = {32, 8, 3, 1};
    cuuint32_t es[4] = {1, 1, 1, 1};
    enc(m, CU_TENSOR_MAP_DATA_TYPE_FLOAT32, 4, (void*)p, dims, strides, box, es,
        CU_TENSOR_MAP_INTERLEAVE_NONE, CU_TENSOR_MAP_SWIZZLE_128B,
        CU_TENSOR_MAP_L2_PROMOTION_L2_128B, CU_TENSOR_MAP_FLOAT_OOB_FILL_NONE);
}

// ---------------- launch ----------------
extern "C" void kernel_launch(void* const* d_in, const int* in_sizes, int n_in,
                              void* d_out, int out_size) {
    const float* feature   = (const float*)d_in[0];
    const int*   x         = (const int*)d_in[1];
    const float* attention = (const float*)d_in[2];
    const float* hiddens   = (const float*)d_in[3];
    const float* emb       = (const float*)d_in[4];
    const float* map_W     = (const float*)d_in[5];
    const float* map_b     = (const float*)d_in[6];
    const float* ai_W      = (const float*)d_in[7];
    const float* ai_b      = (const float*)d_in[8];
    const float* ah_W      = (const float*)d_in[9];
    const float* ah_b      = (const float*)d_in[10];
    const float* ao_W      = (const float*)d_in[11];
    const float* ao_b      = (const float*)d_in[12];
    const float* gru_Wih   = (const float*)d_in[13];
    const float* gru_Whh   = (const float*)d_in[14];
    const float* gru_bih   = (const float*)d_in[15];
    const float* gru_bhh   = (const float*)d_in[16];
    const float* out_W     = (const float*)d_in[17];
    const float* out_b     = (const float*)d_in[18];

    float* out = (float*)d_out;
    float* logp = out;
    float* h1   = out + (size_t)BATCH * VDIM;
    float* nh   = h1 + (size_t)BATCH * HDIM;

    float *ain, *buf0, *buf1, *gh, *hplus;
    cudaGetSymbolAddress((void**)&ain, g_ain);
    cudaGetSymbolAddress((void**)&buf0, g_buf0);
    cudaGetSymbolAddress((void**)&buf1, g_buf1);
    cudaGetSymbolAddress((void**)&gh, g_gh);
    cudaGetSymbolAddress((void**)&hplus, g_hplus);

    EncFn enc = nullptr;
    cudaDriverEntryPointQueryResult qr;
    cudaGetDriverEntryPoint("cuTensorMapEncodeTiled", (void**)&enc,
                            cudaEnableDefault, &qr);
    CUtensorMap mW_gh, mA_gh, mW_out, mA_out, mA_ch, mW_ch;
    make_map3(enc, &mW_gh, gru_Whh, HDIM, 3 * HDIM, NLAYER, 128);
    make_map3(enc, &mA_gh, hplus, HDIM, BATCH, NLAYER, 64);
    make_map3(enc, &mW_out, out_W, HDIM, VDIM, 1, 128);
    make_map3(enc, &mA_out, nh + 7 * (size_t)BH, HDIM, BATCH, 1, 64);
    make_map3(enc, &mA_ch, ain, EDIM, BATCH, NLAYER, 64);
    make_map4_wih(enc, &mW_ch, gru_Wih);

    const int SM_TMA = 1024 + 4 * (64 + 128) * 32 * 4;                        // 99328
    const int SM_CH  = 1024 + 4 * 22528 + (64 * 26 + 64 * 24 + 64 * 8) * 4;  // 105984
    cudaFuncSetAttribute((const void*)gemm_tma,
                         cudaFuncAttributeMaxDynamicSharedMemorySize, SM_TMA);
    cudaFuncSetAttribute((const void*)gru_chain,
                         cudaFuncAttributeMaxDynamicSharedMemorySize, SM_CH);

    // 1) embed into ain[0] (+ barrier init)
    embed_relu_kernel<<<BATCH, 256>>>(emb, x, ain);

    // 2) persistent attention chain; final epilogue writes hplus
    attn_chain<<<HDIM / 16, 256>>>(feature, attention, map_W, map_b, ai_W, ai_b,
                                   ah_W, ah_b, ao_W, ao_b, buf0, buf1,
                                   hiddens, hplus);

    // 3) all 8 gh GEMMs via TMA (192 CTAs)
    gemm_tma<<<dim3(3 * HDIM / 128, NLAYER), 256, SM_TMA>>>(
        mA_gh, mW_gh, gru_bhh, gh, 3 * HDIM, 3 * HDIM);

    // 4) persistent GRU chain with dedicated producer warp (128 CTAs x 416 thr)
    gru_chain<<<128, 416, SM_CH>>>(mA_ch, mW_ch, ain, nh, h1,
                                   gru_bih, gh, hplus);

    // 5) output projection via TMA (250 CTAs) + log-softmax
    gemm_tma<<<dim3(VDIM / 128, 1), 256, SM_TMA>>>(
        mA_out, mW_out, out_b, logp, VDIM, 0);
    log_softmax_kernel<<<BATCH, 1024>>>(logp);
}

// round 15
// speedup vs baseline: 1.4923x; 1.0126x over previous
#include <cuda_runtime.h>
#include <cuda.h>
#include <math.h>
#include <stdint.h>

#define BATCH 64
#define EDIM 1024
#define HDIM 1024
#define FDIM 2048
#define VDIM 32000
#define NLAYER 8
#define BH (BATCH * HDIM)

// ---------------- scratch (no allocation allowed) ----------------
__device__ __align__(16) float g_ain[NLAYER * BATCH * EDIM];
__device__ __align__(16) float g_buf0[BATCH * HDIM];
__device__ __align__(16) float g_buf1[BATCH * HDIM];
__device__ __align__(16) float g_gh[NLAYER * BATCH * 3 * HDIM];
__device__ __align__(16) float g_hplus[NLAYER * BATCH * HDIM];
__device__ int g_bar[NLAYER];
__device__ int g_bar2[4];

// ---------------- ptx helpers ----------------
__device__ __forceinline__ uint32_t tfb(float x) { return __float_as_uint(x); }

__device__ __forceinline__ void cp16(uint32_t saddr, const void* g) {
    asm volatile("cp.async.cg.shared.global [%0], [%1], 16;\n" ::"r"(saddr), "l"(g));
}
__device__ __forceinline__ void cp_commit() { asm volatile("cp.async.commit_group;\n"); }
template <int N>
__device__ __forceinline__ void cp_wait() { asm volatile("cp.async.wait_group %0;\n" ::"n"(N)); }

__device__ __forceinline__ void mbar_init(uint32_t mbar, uint32_t cnt) {
    asm volatile("mbarrier.init.shared.b64 [%0], %1;" ::"r"(mbar), "r"(cnt) : "memory");
}
__device__ __forceinline__ void mbar_expect(uint32_t mbar, uint32_t bytes) {
    asm volatile("mbarrier.arrive.expect_tx.shared.b64 _, [%0], %1;"
                 ::"r"(mbar), "r"(bytes) : "memory");
}
__device__ __forceinline__ void mbar_arrive(uint32_t mbar) {
    asm volatile("mbarrier.arrive.shared.b64 _, [%0];" ::"r"(mbar) : "memory");
}
__device__ __forceinline__ void mbar_wait(uint32_t mbar, uint32_t parity) {
    asm volatile(
        "{\n\t.reg .pred P;\n"
        "LW_%=:\n\t"
        "mbarrier.try_wait.parity.acquire.cta.shared::cta.b64 P, [%0], %1, 0x989680;\n\t"
        "@P bra LD_%=;\n\t"
        "bra LW_%=;\n"
        "LD_%=:\n\t}"
        ::"r"(mbar), "r"(parity) : "memory");
}
__device__ __forceinline__ void tma3(uint32_t dst, const CUtensorMap* map,
                                     int x, int y, int z, uint32_t mbar) {
    asm volatile(
        "cp.async.bulk.tensor.3d.shared::cta.global.tile.mbarrier::complete_tx::bytes "
        "[%0], [%1, {%2, %3, %4}], [%5];"
        ::"r"(dst), "l"(map), "r"(x), "r"(y), "r"(z), "r"(mbar) : "memory");
}
__device__ __forceinline__ void tma4(uint32_t dst, const CUtensorMap* map,
                                     int x, int y, int z, int w, uint32_t mbar) {
    asm volatile(
        "cp.async.bulk.tensor.4d.shared::cta.global.tile.mbarrier::complete_tx::bytes "
        "[%0], [%1, {%2, %3, %4, %5}], [%6];"
        ::"r"(dst), "l"(map), "r"(x), "r"(y), "r"(z), "r"(w), "r"(mbar) : "memory");
}
__device__ __forceinline__ void fence_async() {
    asm volatile("fence.proxy.async;" ::: "memory");
}

__device__ __forceinline__ void mma8(float* c, uint32_t a0, uint32_t a1, uint32_t a2,
                                     uint32_t a3, uint32_t b0, uint32_t b1) {
    asm volatile(
        "mma.sync.aligned.m16n8k8.row.col.f32.tf32.tf32.f32 "
        "{%0,%1,%2,%3}, {%4,%5,%6,%7}, {%8,%9}, {%0,%1,%2,%3};\n"
        : "+f"(c[0]), "+f"(c[1]), "+f"(c[2]), "+f"(c[3])
        : "r"(a0), "r"(a1), "r"(a2), "r"(a3), "r"(b0), "r"(b1));
}

// ---------------- embed (into ain[0]) + barrier init ----------------
__global__ void embed_relu_kernel(const float* __restrict__ emb,
                                  const int* __restrict__ x,
                                  float* __restrict__ ain0) {
    if (blockIdx.x == 0) {
        const int t = threadIdx.x;
        if (t < NLAYER) g_bar[t] = 0;
        else if (t < NLAYER + 4) g_bar2[t - NLAYER] = 0;
    }
    const int b = blockIdx.x;
    const int row = x[b];
    const float* src = emb + (size_t)row * EDIM;
    float* dst = ain0 + (size_t)b * EDIM;
    for (int e = threadIdx.x; e < EDIM; e += blockDim.x) {
        float v = src[e];
        dst[e] = v > 0.f ? v : 0.f;
    }
}

// ---------------- persistent attention chain (cp.async, 64 blocks) ----------------
__global__ __launch_bounds__(256) void attn_chain(
    const float* __restrict__ feature, const float* __restrict__ attention,
    const float* __restrict__ mapW, const float* __restrict__ mapb,
    const float* __restrict__ aiW, const float* __restrict__ aib,
    const float* __restrict__ ahW, const float* __restrict__ ahb,
    const float* __restrict__ aoW, const float* __restrict__ aob,
    float* __restrict__ buf0, float* __restrict__ buf1,
    const float* __restrict__ hiddens, float* __restrict__ hplus) {
    constexpr int S = 3, LDT = 36, BN = 16;
    __shared__ float As[S * 64 * LDT];
    __shared__ float Ws[S * BN * LDT];

    const float* Aptr[4] = {feature, buf0, buf1, buf0};
    const float* Wptr[4] = {mapW, aiW, ahW, aoW};
    const float* bptr[4] = {mapb, aib, ahb, aob};
    float* optr[3] = {buf0, buf1, buf0};
    const int Ks[4] = {FDIM, HDIM, HDIM, HDIM};

    const int tid = threadIdx.x, lane = tid & 31, warp = tid >> 5;
    const int wm = warp & 3, wn = warp >> 2;
    const int r = lane >> 2, kk = lane & 3;
    const int nBlock = blockIdx.x * BN;

    const uint32_t sA = (uint32_t)__cvta_generic_to_shared(As);
    const uint32_t sW = (uint32_t)__cvta_generic_to_shared(Ws);

    for (int layer = 0; layer < 4; layer++) {
        const float* A = Aptr[layer];
        const float* W = Wptr[layer];
        const int K = Ks[layer];
        const int nK = K / 32;

        auto issue = [&](int st, int k0) {
#pragma unroll
            for (int t = 0; t < 2; t++) {
                const int idx = tid + t * 256;
                const int m = idx >> 3, k4 = idx & 7;
                cp16(sA + (uint32_t)(((st * 64 + m) * LDT + k4 * 4) * 4),
                     A + (size_t)m * K + k0 + k4 * 4);
            }
            if (tid < BN * 8) {
                const int wr = tid >> 3, k4 = tid & 7;
                cp16(sW + (uint32_t)(((st * BN + wr) * LDT + k4 * 4) * 4),
                     W + (size_t)(nBlock + wr) * K + k0 + k4 * 4);
            }
        };

#pragma unroll
        for (int p = 0; p < S - 1; p++) {
            if (p < nK) issue(p, p * 32);
            cp_commit();
        }

        float acc[4] = {0.f, 0.f, 0.f, 0.f};
        for (int kt = 0; kt < nK; kt++) {
            cp_wait<S - 2>();
            __syncthreads();
            const int pf = kt + S - 1;
            if (pf < nK) issue(pf % S, pf * 32);
            cp_commit();
            const float* a_ = As + (kt % S) * 64 * LDT;
            const float* w_ = Ws + (kt % S) * BN * LDT;
#pragma unroll
            for (int s = 0; s < 4; s++) {
                const int col = s * 8 + kk;
                const uint32_t a0 = tfb(a_[(wm * 16 + r) * LDT + col]);
                const uint32_t a1 = tfb(a_[(wm * 16 + r + 8) * LDT + col]);
                const uint32_t a2 = tfb(a_[(wm * 16 + r) * LDT + col + 4]);
                const uint32_t a3 = tfb(a_[(wm * 16 + r + 8) * LDT + col + 4]);
                const int n = wn * 8 + r;
                mma8(acc, a0, a1, a2, a3, tfb(w_[n * LDT + col]),
                     tfb(w_[n * LDT + col + 4]));
            }
        }
        cp_wait<0>();

        const int row0 = wm * 16 + r;
        const int col = nBlock + wn * 8 + 2 * kk;
        const float b0v = bptr[layer][col], b1v = bptr[layer][col + 1];
        float v0 = fmaxf(acc[0] + b0v, 0.f), v1 = fmaxf(acc[1] + b1v, 0.f);
        float v2 = fmaxf(acc[2] + b0v, 0.f), v3 = fmaxf(acc[3] + b1v, 0.f);
        if (layer == 0) {
            v0 += attention[(size_t)row0 * HDIM + col];
            v1 += attention[(size_t)row0 * HDIM + col + 1];
            v2 += attention[(size_t)(row0 + 8) * HDIM + col];
            v3 += attention[(size_t)(row0 + 8) * HDIM + col + 1];
        }
        if (layer < 3) {
            float* o = optr[layer];
            *reinterpret_cast<float2*>(o + (size_t)row0 * HDIM + col) = make_float2(v0, v1);
            *reinterpret_cast<float2*>(o + (size_t)(row0 + 8) * HDIM + col) = make_float2(v2, v3);
        } else {
#pragma unroll
            for (int l = 0; l < NLAYER; l++) {
                const size_t b0i = (size_t)l * BH + (size_t)row0 * HDIM + col;
                const size_t b1i = (size_t)l * BH + (size_t)(row0 + 8) * HDIM + col;
                float2 h0 = *reinterpret_cast<const float2*>(hiddens + b0i);
                float2 h8 = *reinterpret_cast<const float2*>(hiddens + b1i);
                *reinterpret_cast<float2*>(hplus + b0i) = make_float2(h0.x + v0, h0.y + v1);
                *reinterpret_cast<float2*>(hplus + b1i) = make_float2(h8.x + v2, h8.y + v3);
            }
            fence_async();
        }

        if (layer < 3) {
            __threadfence();
            __syncthreads();
            if (tid == 0) {
                atomicAdd(&g_bar2[layer], 1);
                while (atomicAdd(&g_bar2[layer], 0) < (int)gridDim.x) __nanosleep(32);
            }
            __syncthreads();
        }
    }
}

// ---------------- TMA GEMM v2: producer warp, no per-stage syncthreads ----------
// 288 threads = 8 consumer warps + warp 8 producer. BN=128, K=1024 (32 stages).
// full[s] at sb+s*16 (count=1, tx covers A+W), empty[s] at sb+s*16+8 (count=8).
__global__ __launch_bounds__(288) void gemm_tma(
    const __grid_constant__ CUtensorMap mapA,
    const __grid_constant__ CUtensorMap mapW,
    const float* __restrict__ bias, float* __restrict__ out,
    int N, int biasStride) {
    constexpr int BN = 128;
    constexpr int STG = (64 + BN) * 32 * 4;   // 24576
    extern __shared__ float sm[];
    const uint32_t sb = (uint32_t)__cvta_generic_to_shared(sm);
    const uint32_t tiles = sb + 1024;

    const int tid = threadIdx.x, lane = tid & 31, warp = tid >> 5;
    const int wm = warp & 3, wn = (warp >> 2) & 1;
    const int r = lane >> 2, kk = lane & 3;
    const int nBlock = blockIdx.x * BN;
    const int layer = blockIdx.y;
    const bool producer = (warp == 8);

    bias += (size_t)layer * biasStride;
    out += (size_t)layer * BATCH * N;

    if (tid == 0) {
#pragma unroll
        for (int s = 0; s < 4; s++) {
            mbar_init(sb + s * 16, 1);       // full (tx-based)
            mbar_init(sb + s * 16 + 8, 8);   // empty (8 consumer warps)
        }
    }
    __syncthreads();

    if (producer && lane == 0) {
        for (int kt = 0; kt < 32; kt++) {
            const int s = kt & 3, n = kt >> 2;
            if (n > 0) mbar_wait(sb + s * 16 + 8, (n - 1) & 1);
            const uint32_t mb = sb + s * 16;
            mbar_expect(mb, STG);
            const uint32_t dA = tiles + s * STG;
            tma3(dA, &mapA, kt * 32, 0, layer, mb);
            tma3(dA + 64 * 128, &mapW, kt * 32, nBlock, layer, mb);
        }
        return;
    }
    if (producer) return;

    float acc[8][4];
#pragma unroll
    for (int i = 0; i < 8; i++)
#pragma unroll
        for (int j = 0; j < 4; j++) acc[i][j] = 0.f;

    const int swz = r << 2;
    for (int kt = 0; kt < 32; kt++) {
        const int s = kt & 3;
        mbar_wait(sb + s * 16, (kt >> 2) & 1);
        const float* a_ = sm + 256 + s * (STG / 4);
        const float* w_ = a_ + 64 * 32;
#pragma unroll
        for (int q = 0; q < 4; q++) {
            const int col = (q * 8 + kk) ^ swz;
            const int col4 = col ^ 4;
            const int m0 = wm * 16 + r;
            const uint32_t a0 = tfb(a_[m0 * 32 + col]);
            const uint32_t a1 = tfb(a_[(m0 + 8) * 32 + col]);
            const uint32_t a2 = tfb(a_[m0 * 32 + col4]);
            const uint32_t a3 = tfb(a_[(m0 + 8) * 32 + col4]);
#pragma unroll
            for (int nt = 0; nt < 8; nt++) {
                const int n = wn * 64 + nt * 8 + r;
                mma8(acc[nt], a0, a1, a2, a3, tfb(w_[n * 32 + col]),
                     tfb(w_[n * 32 + col4]));
            }
        }
        if (lane == 0) mbar_arrive(sb + s * 16 + 8);
    }

    const int row0 = wm * 16 + r;
#pragma unroll
    for (int nt = 0; nt < 8; nt++) {
        const int col = nBlock + wn * 64 + nt * 8 + 2 * kk;
        const float b0v = bias[col], b1v = bias[col + 1];
        *reinterpret_cast<float2*>(out + (size_t)row0 * N + col) =
            make_float2(acc[nt][0] + b0v, acc[nt][1] + b1v);
        *reinterpret_cast<float2*>(out + (size_t)(row0 + 8) * N + col) =
            make_float2(acc[nt][2] + b0v, acc[nt][3] + b1v);
    }
}

// ---------------- persistent fused GRU chain v9: dedicated producer warp ----------
__global__ __launch_bounds__(416) void gru_chain(
    const __grid_constant__ CUtensorMap mapA,
    const __grid_constant__ CUtensorMap mapW,
    float* __restrict__ ain, float* __restrict__ nh, float* __restrict__ h1,
    const float* __restrict__ gru_bih, const float* __restrict__ gh,
    const float* __restrict__ hplus) {
    constexpr int SLOT = 22528;   // A 16384 + W 6144
    constexpr int CLD = 26;
    extern __shared__ float sm[];
    const uint32_t sb = (uint32_t)__cvta_generic_to_shared(sm);
    const uint32_t tiles = sb + 1024;
    float* Cs = sm + 256 + 4 * (SLOT / 4);
    float* ghs = Cs + 64 * CLD;
    float* hps = ghs + 64 * 24;
    const uint32_t sGh = (uint32_t)__cvta_generic_to_shared(ghs);
    const uint32_t sHp = (uint32_t)__cvta_generic_to_shared(hps);

    const int g = blockIdx.x;
    const int h0 = g * 8;
    const int tid = threadIdx.x, lane = tid & 31, warp = tid >> 5;
    const int wm = warp & 3, sec = warp >> 2;
    const int r = lane >> 2, kk = lane & 3;
    const int swz = r << 2;
    const bool producer = (warp == 12);

    if (tid == 0) {
#pragma unroll
        for (int s = 0; s < 4; s++) {
            mbar_init(sb + s * 16, 2);
            mbar_init(sb + s * 16 + 8, 12);
        }
    }
    __syncthreads();

    auto fillW = [&](int gidx) {
        const int s = gidx & 3;
        const int n = gidx >> 2;
        if (n > 0) mbar_wait(sb + s * 16 + 8, (n - 1) & 1);
        const uint32_t mb = sb + s * 16;
        mbar_expect(mb, 6144);
        const int layer = gidx >> 4, kt = gidx & 15;
        const int x0 = kt * 64;
        const uint32_t dst = tiles + s * SLOT + 16384;
        tma4(dst, &mapW, x0, h0, 0, layer, mb);
        tma4(dst + 3072, &mapW, x0 + 32, h0, 0, layer, mb);
    };
    auto fillA = [&](int gidx) {
        const int s = gidx & 3;
        const uint32_t mb = sb + s * 16;
        mbar_expect(mb, 16384);
        const int layer = gidx >> 4, kt = gidx & 15;
        const int x0 = kt * 64;
        const uint32_t dst = tiles + s * SLOT;
        tma3(dst, &mapA, x0, 0, layer, mb);
        tma3(dst + 8192, &mapA, x0 + 32, 0, layer, mb);
    };

    if (producer && lane == 0) {
        fillW(0); fillA(0); fillW(1); fillA(1); fillW(2); fillA(2);
    }

    float prev[2];

    for (int layer = 0; layer < NLAYER; layer++) {
        const float* bih = gru_bih + (size_t)layer * 3 * HDIM;
        float* outh = nh + (size_t)layer * BH;
        float* ainN = ain + (size_t)(layer + 1) * BH;
        const int g0 = layer * 16;

        {
            const int pair = tid >> 1, half = tid & 1;
            if (pair < 192) {
                const int b = pair / 3, gate = pair % 3;
                cp16(sGh + (uint32_t)((b * 24 + gate * 8 + half * 4) * 4),
                     gh + (size_t)layer * BATCH * 3 * HDIM + (size_t)b * 3 * HDIM +
                         gate * HDIM + h0 + half * 4);
            }
            if (tid < 128) {
                const int b = tid >> 1, half = tid & 1;
                cp16(sHp + (uint32_t)((b * 8 + half * 4) * 4),
                     hplus + (size_t)layer * BH + (size_t)b * HDIM + h0 + half * 4);
            }
            cp_commit();
        }

        if (!producer) {
            float acc[4] = {0.f, 0.f, 0.f, 0.f};
            for (int kt = 0; kt < 16; kt++) {
                const int gidx = g0 + kt;
                const int s = gidx & 3;
                mbar_wait(sb + s * 16, (gidx >> 2) & 1);
                const float* stg = sm + 256 + s * (SLOT / 4);
#pragma unroll
                for (int q = 0; q < 8; q++) {
                    const int p = q >> 2;
                    const float* a_ = stg + p * 2048;
                    const float* w_ = stg + 4096 + p * 768;
                    const int col = ((q & 3) * 8 + kk) ^ swz;
                    const int col4 = col ^ 4;
                    const int m0 = wm * 16 + r;
                    const uint32_t a0 = tfb(a_[m0 * 32 + col]);
                    const uint32_t a1 = tfb(a_[(m0 + 8) * 32 + col]);
                    const uint32_t a2 = tfb(a_[m0 * 32 + col4]);
                    const uint32_t a3 = tfb(a_[(m0 + 8) * 32 + col4]);
                    const int brow = sec * 8 + r;
                    mma8(acc, a0, a1, a2, a3, tfb(w_[brow * 32 + col]),
                         tfb(w_[brow * 32 + col4]));
                }
                if (lane == 0) mbar_arrive(sb + s * 16 + 8);
            }
            const int row0 = wm * 16 + r;
            const int cl = sec * 8 + 2 * kk;
            *reinterpret_cast<float2*>(&Cs[row0 * CLD + cl]) =
                make_float2(acc[0], acc[1]);
            *reinterpret_cast<float2*>(&Cs[(row0 + 8) * CLD + cl]) =
                make_float2(acc[2], acc[3]);
        } else if (lane == 0) {
            for (int kt = 0; kt < 16; kt++) {
                if (layer == 0 && kt < 3) continue;
                const int gidx = g0 + kt;
                if (kt < 3) {
                    fillA(gidx);
                } else {
                    fillW(gidx); fillA(gidx);
                }
            }
            if (layer < NLAYER - 1) {
                fillW(g0 + 16); fillW(g0 + 17); fillW(g0 + 18);
            }
        }

        cp_wait<0>();
        __syncthreads();

        int t = 0;
        for (int idx = tid; idx < 512; idx += 416, t++) {
            const int b = idx >> 3, hh = idx & 7;
            const int h = h0 + hh;
            const float ir = Cs[b * CLD + hh] + bih[h];
            const float iz = Cs[b * CLD + 8 + hh] + bih[HDIM + h];
            const float in_ = Cs[b * CLD + 16 + hh] + bih[2 * HDIM + h];
            const float rr = 1.f / (1.f + expf(-(ir + ghs[b * 24 + hh])));
            const float zz = 1.f / (1.f + expf(-(iz + ghs[b * 24 + 8 + hh])));
            const float nn = tanhf(in_ + rr * ghs[b * 24 + 16 + hh]);
            const float hp = hps[b * 8 + hh];
            const float o = (1.f - zz) * nn + zz * hp;
            outh[(size_t)b * HDIM + h] = o;
            if (layer == 0) h1[(size_t)b * HDIM + h] = o;
            if (layer < NLAYER - 1) {
                const float nx = (layer < 2) ? o : (o + prev[t]);
                ainN[(size_t)b * HDIM + h] = nx;
            }
            prev[t] = o;
        }

        if (layer < NLAYER - 1) {
            __threadfence();
            fence_async();
            __syncthreads();
            if (tid == 0) {
                atomicAdd(&g_bar[layer], 1);
                while (atomicAdd(&g_bar[layer], 0) < (int)gridDim.x) __nanosleep(32);
            }
            __syncthreads();
        }
    }
}

// ---------------- 2-pass online log_softmax ----------------
__global__ __launch_bounds__(1024) void log_softmax_kernel(float* __restrict__ logits) {
    const int b = blockIdx.x;
    float* row = logits + (size_t)b * VDIM;
    __shared__ float smax[32], ssum[32];
    __shared__ float s_lse;
    const int lane = threadIdx.x & 31;
    const int wid = threadIdx.x >> 5;

    float m = -1e30f, s = 0.f;
    const float4* r4 = reinterpret_cast<const float4*>(row);
    for (int v = threadIdx.x; v < VDIM / 4; v += blockDim.x) {
        float4 x = r4[v];
#define ONE(val) { float d = (val) - m; \
        if (d > 0.f) { s = s * __expf(-d) + 1.f; m = (val); } else s += __expf(d); }
        ONE(x.x) ONE(x.y) ONE(x.z) ONE(x.w)
#undef ONE
    }
#pragma unroll
    for (int o = 16; o; o >>= 1) {
        float mo = __shfl_xor_sync(0xffffffffu, m, o);
        float so = __shfl_xor_sync(0xffffffffu, s, o);
        float mn = fmaxf(m, mo);
        s = s * __expf(m - mn) + so * __expf(mo - mn);
        m = mn;
    }
    if (lane == 0) { smax[wid] = m; ssum[wid] = s; }
    __syncthreads();
    if (wid == 0) {
        float mm = (lane < (blockDim.x >> 5)) ? smax[lane] : -1e30f;
        float ss = (lane < (blockDim.x >> 5)) ? ssum[lane] : 0.f;
#pragma unroll
        for (int o = 16; o; o >>= 1) {
            float mo = __shfl_xor_sync(0xffffffffu, mm, o);
            float so = __shfl_xor_sync(0xffffffffu, ss, o);
            float mn = fmaxf(mm, mo);
            ss = ss * __expf(mm - mn) + so * __expf(mo - mn);
            mm = mn;
        }
        if (lane == 0) s_lse = mm + logf(ss);
    }
    __syncthreads();
    const float lse = s_lse;
    float4* w4 = reinterpret_cast<float4*>(row);
    for (int v = threadIdx.x; v < VDIM / 4; v += blockDim.x) {
        float4 x = w4[v];
        x.x -= lse; x.y -= lse; x.z -= lse; x.w -= lse;
        w4[v] = x;
    }
}

// ---------------- host-side tensormap encoding ----------------
typedef CUresult (CUDAAPI* EncFn)(
    CUtensorMap*, CUtensorMapDataType, cuuint32_t, void*,
    const cuuint64_t*, const cuuint64_t*, const cuuint32_t*, const cuuint32_t*,
    CUtensorMapInterleave, CUtensorMapSwizzle, CUtensorMapL2promotion,
    CUtensorMapFloatOOBfill);

static void make_map3(EncFn enc, CUtensorMap* m, const void* p,
                      unsigned long long d0, unsigned long long d1,
                      unsigned long long d2, unsigned int b1) {
    cuuint64_t dims[3] = {d0, d1, d2};
    cuuint64_t strides[2] = {d0 * 4, d0 * d1 * 4};
    cuuint32_t box[3] = {32, b1, 1};
    cuuint32_t es[3] = {1, 1, 1};
    enc(m, CU_TENSOR_MAP_DATA_TYPE_FLOAT32, 3, (void*)p, dims, strides, box, es,
        CU_TENSOR_MAP_INTERLEAVE_NONE, CU_TENSOR_MAP_SWIZZLE_128B,
        CU_TENSOR_MAP_L2_PROMOTION_L2_128B, CU_TENSOR_MAP_FLOAT_OOB_FILL_NONE);
}

static void make_map4_wih(EncFn enc, CUtensorMap* m, const void* p) {
    cuuint64_t dims[4] = {EDIM, HDIM, 3, NLAYER};
    cuuint64_t strides[3] = {(cuuint64_t)EDIM * 4,
                             (cuuint64_t)HDIM * EDIM * 4,
                             (cuuint64_t)3 * HDIM * EDIM * 4};
    cuuint32_t box[4] = {32, 8, 3, 1};
    cuuint32_t es[4] = {1, 1, 1, 1};
    enc(m, CU_TENSOR_MAP_DATA_TYPE_FLOAT32, 4, (void*)p, dims, strides, box, es,
        CU_TENSOR_MAP_INTERLEAVE_NONE, CU_TENSOR_MAP_SWIZZLE_128B,
        CU_TENSOR_MAP_L2_PROMOTION_L2_128B, CU_TENSOR_MAP_FLOAT_OOB_FILL_NONE);
}

// ---------------- launch ----------------
extern "C" void kernel_launch(void* const* d_in, const int* in_sizes, int n_in,
                              void* d_out, int out_size) {
    const float* feature   = (const float*)d_in[0];
    const int*   x         = (const int*)d_in[1];
    const float* attention = (const float*)d_in[2];
    const float* hiddens   = (const float*)d_in[3];
    const float* emb       = (const float*)d_in[4];
    const float* map_W     = (const float*)d_in[5];
    const float* map_b     = (const float*)d_in[6];
    const float* ai_W      = (const float*)d_in[7];
    const float* ai_b      = (const float*)d_in[8];
    const float* ah_W      = (const float*)d_in[9];
    const float* ah_b      = (const float*)d_in[10];
    const float* ao_W      = (const float*)d_in[11];
    const float* ao_b      = (const float*)d_in[12];
    const float* gru_Wih   = (const float*)d_in[13];
    const float* gru_Whh   = (const float*)d_in[14];
    const float* gru_bih   = (const float*)d_in[15];
    const float* gru_bhh   = (const float*)d_in[16];
    const float* out_W     = (const float*)d_in[17];
    const float* out_b     = (const float*)d_in[18];

    float* out = (float*)d_out;
    float* logp = out;
    float* h1   = out + (size_t)BATCH * VDIM;
    float* nh   = h1 + (size_t)BATCH * HDIM;

    float *ain, *buf0, *buf1, *gh, *hplus;
    cudaGetSymbolAddress((void**)&ain, g_ain);
    cudaGetSymbolAddress((void**)&buf0, g_buf0);
    cudaGetSymbolAddress((void**)&buf1, g_buf1);
    cudaGetSymbolAddress((void**)&gh, g_gh);
    cudaGetSymbolAddress((void**)&hplus, g_hplus);

    EncFn enc = nullptr;
    cudaDriverEntryPointQueryResult qr;
    cudaGetDriverEntryPoint("cuTensorMapEncodeTiled", (void**)&enc,
                            cudaEnableDefault, &qr);
    CUtensorMap mW_gh, mA_gh, mW_out, mA_out, mA_ch, mW_ch;
    make_map3(enc, &mW_gh, gru_Whh, HDIM, 3 * HDIM, NLAYER, 128);
    make_map3(enc, &mA_gh, hplus, HDIM, BATCH, NLAYER, 64);
    make_map3(enc, &mW_out, out_W, HDIM, VDIM, 1, 128);
    make_map3(enc, &mA_out, nh + 7 * (size_t)BH, HDIM, BATCH, 1, 64);
    make_map3(enc, &mA_ch, ain, EDIM, BATCH, NLAYER, 64);
    make_map4_wih(enc, &mW_ch, gru_Wih);

    const int SM_TMA = 1024 + 4 * (64 + 128) * 32 * 4;                        // 99328
    const int SM_CH  = 1024 + 4 * 22528 + (64 * 26 + 64 * 24 + 64 * 8) * 4;  // 105984
    cudaFuncSetAttribute((const void*)gemm_tma,
                         cudaFuncAttributeMaxDynamicSharedMemorySize, SM_TMA);
    cudaFuncSetAttribute((const void*)gru_chain,
                         cudaFuncAttributeMaxDynamicSharedMemorySize, SM_CH);

    // 1) embed into ain[0] (+ barrier init)
    embed_relu_kernel<<<BATCH, 256>>>(emb, x, ain);

    // 2) persistent attention chain; final epilogue writes hplus
    attn_chain<<<HDIM / 16, 256>>>(feature, attention, map_W, map_b, ai_W, ai_b,
                                   ah_W, ah_b, ao_W, ao_b, buf0, buf1,
                                   hiddens, hplus);

    // 3) all 8 gh GEMMs via TMA + producer warp (192 CTAs)
    gemm_tma<<<dim3(3 * HDIM / 128, NLAYER), 288, SM_TMA>>>(
        mA_gh, mW_gh, gru_bhh, gh, 3 * HDIM, 3 * HDIM);

    // 4) persistent GRU chain with dedicated producer warp (128 CTAs x 416 thr)
    gru_chain<<<128, 416, SM_CH>>>(mA_ch, mW_ch, ain, nh, h1,
                                   gru_bih, gh, hplus);

    // 5) output projection via TMA + producer warp (250 CTAs) + log-softmax
    gemm_tma<<<dim3(VDIM / 128, 1), 288, SM_TMA>>>(
        mA_out, mW_out, out_b, logp, VDIM, 0);
    log_softmax_kernel<<<BATCH, 1024>>>(logp);
}

// round 16
// speedup vs baseline: 1.7623x; 1.1809x over previous
#include <cuda_runtime.h>
#include <cuda.h>
#include <math.h>
#include <stdint.h>

#define BATCH 64
#define EDIM 1024
#define HDIM 1024
#define FDIM 2048
#define VDIM 32000
#define NLAYER 8
#define BH (BATCH * HDIM)

// ---------------- scratch (no allocation allowed) ----------------
__device__ __align__(16) float g_ain[NLAYER * BATCH * EDIM];
__device__ __align__(16) float g_buf0[BATCH * HDIM];
__device__ __align__(16) float g_buf1[BATCH * HDIM];
__device__ __align__(16) float g_gh[NLAYER * BATCH * 3 * HDIM];
__device__ __align__(16) float g_hplus[NLAYER * BATCH * HDIM];
__device__ int g_bar[NLAYER];
__device__ int g_bar2[4];

// ---------------- ptx helpers ----------------
__device__ __forceinline__ uint32_t tfb(float x) { return __float_as_uint(x); }

__device__ __forceinline__ void cp16(uint32_t saddr, const void* g) {
    asm volatile("cp.async.cg.shared.global [%0], [%1], 16;\n" ::"r"(saddr), "l"(g));
}
__device__ __forceinline__ void cp_commit() { asm volatile("cp.async.commit_group;\n"); }
template <int N>
__device__ __forceinline__ void cp_wait() { asm volatile("cp.async.wait_group %0;\n" ::"n"(N)); }

__device__ __forceinline__ void mbar_init(uint32_t mbar, uint32_t cnt) {
    asm volatile("mbarrier.init.shared.b64 [%0], %1;" ::"r"(mbar), "r"(cnt) : "memory");
}
__device__ __forceinline__ void mbar_expect(uint32_t mbar, uint32_t bytes) {
    asm volatile("mbarrier.arrive.expect_tx.shared.b64 _, [%0], %1;"
                 ::"r"(mbar), "r"(bytes) : "memory");
}
__device__ __forceinline__ void mbar_arrive(uint32_t mbar) {
    asm volatile("mbarrier.arrive.shared.b64 _, [%0];" ::"r"(mbar) : "memory");
}
__device__ __forceinline__ void mbar_wait(uint32_t mbar, uint32_t parity) {
    asm volatile(
        "{\n\t.reg .pred P;\n"
        "LW_%=:\n\t"
        "mbarrier.try_wait.parity.acquire.cta.shared::cta.b64 P, [%0], %1, 0x989680;\n\t"
        "@P bra LD_%=;\n\t"
        "bra LW_%=;\n"
        "LD_%=:\n\t}"
        ::"r"(mbar), "r"(parity) : "memory");
}
__device__ __forceinline__ void tma3(uint32_t dst, const CUtensorMap* map,
                                     int x, int y, int z, uint32_t mbar) {
    asm volatile(
        "cp.async.bulk.tensor.3d.shared::cta.global.tile.mbarrier::complete_tx::bytes "
        "[%0], [%1, {%2, %3, %4}], [%5];"
        ::"r"(dst), "l"(map), "r"(x), "r"(y), "r"(z), "r"(mbar) : "memory");
}
__device__ __forceinline__ void tma4(uint32_t dst, const CUtensorMap* map,
                                     int x, int y, int z, int w, uint32_t mbar) {
    asm volatile(
        "cp.async.bulk.tensor.4d.shared::cta.global.tile.mbarrier::complete_tx::bytes "
        "[%0], [%1, {%2, %3, %4, %5}], [%6];"
        ::"r"(dst), "l"(map), "r"(x), "r"(y), "r"(z), "r"(w), "r"(mbar) : "memory");
}
__device__ __forceinline__ void fence_async() {
    asm volatile("fence.proxy.async;" ::: "memory");
}

__device__ __forceinline__ void mma8(float* c, uint32_t a0, uint32_t a1, uint32_t a2,
                                     uint32_t a3, uint32_t b0, uint32_t b1) {
    asm volatile(
        "mma.sync.aligned.m16n8k8.row.col.f32.tf32.tf32.f32 "
        "{%0,%1,%2,%3}, {%4,%5,%6,%7}, {%8,%9}, {%0,%1,%2,%3};\n"
        : "+f"(c[0]), "+f"(c[1]), "+f"(c[2]), "+f"(c[3])
        : "r"(a0), "r"(a1), "r"(a2), "r"(a3), "r"(b0), "r"(b1));
}

// ---------------- embed (into ain[0]) + barrier init ----------------
__global__ void embed_relu_kernel(const float* __restrict__ emb,
                                  const int* __restrict__ x,
                                  float* __restrict__ ain0) {
    if (blockIdx.x == 0) {
        const int t = threadIdx.x;
        if (t < NLAYER) g_bar[t] = 0;
        else if (t < NLAYER + 4) g_bar2[t - NLAYER] = 0;
    }
    const int b = blockIdx.x;
    const int row = x[b];
    const float* src = emb + (size_t)row * EDIM;
    float* dst = ain0 + (size_t)b * EDIM;
    for (int e = threadIdx.x; e < EDIM; e += blockDim.x) {
        float v = src[e];
        dst[e] = v > 0.f ? v : 0.f;
    }
}

// ---------------- attention chain v2: TMA + producer warp (64 CTAs x 288 thr) -------
// 4 layers; BK=64 double-panel stages: layer0 32 stages (K=2048), layers1-3 16 each.
// full[s]: count=2 (W fill + A fill). empty[s]: count=8 (consumer warps).
__global__ __launch_bounds__(288) void attn_chain(
    const __grid_constant__ CUtensorMap mFeat,
    const __grid_constant__ CUtensorMap mB0,
    const __grid_constant__ CUtensorMap mB1,
    const __grid_constant__ CUtensorMap mW0,
    const __grid_constant__ CUtensorMap mW1,
    const __grid_constant__ CUtensorMap mW2,
    const __grid_constant__ CUtensorMap mW3,
    const float* __restrict__ attention,
    const float* __restrict__ mapb, const float* __restrict__ aib,
    const float* __restrict__ ahb, const float* __restrict__ aob,
    float* __restrict__ buf0, float* __restrict__ buf1,
    const float* __restrict__ hiddens, float* __restrict__ hplus) {
    constexpr int BN = 16;
    constexpr int SLOT = 20480;   // A 16384 + W 4096
    extern __shared__ float sm[];
    const uint32_t sb = (uint32_t)__cvta_generic_to_shared(sm);
    const uint32_t tiles = sb + 1024;

    const CUtensorMap* amaps[4] = {&mFeat, &mB0, &mB1, &mB0};
    const CUtensorMap* wmaps[4] = {&mW0, &mW1, &mW2, &mW3};
    const float* bptr[4] = {mapb, aib, ahb, aob};
    float* optr[3] = {buf0, buf1, buf0};
    const int nSt[4] = {32, 16, 16, 16};
    const int gsBase[4] = {0, 32, 48, 64};

    const int tid = threadIdx.x, lane = tid & 31, warp = tid >> 5;
    const int wm = warp & 3, wn = (warp >> 2) & 1;
    const int r = lane >> 2, kk = lane & 3;
    const int swz = r << 2;
    const int nBlock = blockIdx.x * BN;
    const bool producer = (warp == 8);

    if (tid == 0) {
#pragma unroll
        for (int s = 0; s < 4; s++) {
            mbar_init(sb + s * 16, 2);       // full (W + A arrivals)
            mbar_init(sb + s * 16 + 8, 8);   // empty (8 consumer warps)
        }
    }
    __syncthreads();

    auto fillW = [&](int gs, int layer, int kt) {
        const int s = gs & 3;
        const int n = gs >> 2;
        if (n > 0) mbar_wait(sb + s * 16 + 8, (n - 1) & 1);
        const uint32_t mb = sb + s * 16;
        mbar_expect(mb, 4096);
        const int x0 = kt * 64;
        const uint32_t dst = tiles + s * SLOT + 16384;
        tma3(dst, wmaps[layer], x0, nBlock, 0, mb);
        tma3(dst + 2048, wmaps[layer], x0 + 32, nBlock, 0, mb);
    };
    auto fillA = [&](int gs, int layer, int kt) {
        const int s = gs & 3;
        const uint32_t mb = sb + s * 16;
        mbar_expect(mb, 16384);
        const int x0 = kt * 64;
        const uint32_t dst = tiles + s * SLOT;
        tma3(dst, amaps[layer], x0, 0, 0, mb);
        tma3(dst + 8192, amaps[layer], x0 + 32, 0, 0, mb);
    };

    if (producer && lane == 0) {
        fillW(0, 0, 0); fillA(0, 0, 0);
        fillW(1, 0, 1); fillA(1, 0, 1);
        fillW(2, 0, 2); fillA(2, 0, 2);
    }

    for (int layer = 0; layer < 4; layer++) {
        const int g0 = gsBase[layer];
        const int ns = nSt[layer];

        float acc[4] = {0.f, 0.f, 0.f, 0.f};
        if (!producer) {
            for (int kt = 0; kt < ns; kt++) {
                const int gs = g0 + kt;
                const int s = gs & 3;
                mbar_wait(sb + s * 16, (gs >> 2) & 1);
                const float* stg = sm + 256 + s * (SLOT / 4);
#pragma unroll
                for (int q = 0; q < 8; q++) {
                    const int p = q >> 2;
                    const float* a_ = stg + p * 2048;
                    const float* w_ = stg + 4096 + p * 512;
                    const int col = ((q & 3) * 8 + kk) ^ swz;
                    const int col4 = col ^ 4;
                    const int m0 = wm * 16 + r;
                    const uint32_t a0 = tfb(a_[m0 * 32 + col]);
                    const uint32_t a1 = tfb(a_[(m0 + 8) * 32 + col]);
                    const uint32_t a2 = tfb(a_[m0 * 32 + col4]);
                    const uint32_t a3 = tfb(a_[(m0 + 8) * 32 + col4]);
                    const int brow = wn * 8 + r;
                    mma8(acc, a0, a1, a2, a3, tfb(w_[brow * 32 + col]),
                         tfb(w_[brow * 32 + col4]));
                }
                if (lane == 0) mbar_arrive(sb + s * 16 + 8);
            }
        } else if (lane == 0) {
            for (int kt = 0; kt < ns; kt++) {
                if (layer == 0 && kt < 3) continue;
                const int gs = g0 + kt;
                if (kt < 3) {
                    fillA(gs, layer, kt);
                } else {
                    fillW(gs, layer, kt); fillA(gs, layer, kt);
                }
            }
            if (layer < 3) {   // next layer W prefetch (crosses the grid barrier)
                fillW(gsBase[layer + 1], layer + 1, 0);
                fillW(gsBase[layer + 1] + 1, layer + 1, 1);
                fillW(gsBase[layer + 1] + 2, layer + 1, 2);
            }
        }

        // epilogue (consumer warps only)
        if (!producer) {
            const int row0 = wm * 16 + r;
            const int col = nBlock + wn * 8 + 2 * kk;
            const float b0v = bptr[layer][col], b1v = bptr[layer][col + 1];
            float v0 = fmaxf(acc[0] + b0v, 0.f), v1 = fmaxf(acc[1] + b1v, 0.f);
            float v2 = fmaxf(acc[2] + b0v, 0.f), v3 = fmaxf(acc[3] + b1v, 0.f);
            if (layer == 0) {
                v0 += attention[(size_t)row0 * HDIM + col];
                v1 += attention[(size_t)row0 * HDIM + col + 1];
                v2 += attention[(size_t)(row0 + 8) * HDIM + col];
                v3 += attention[(size_t)(row0 + 8) * HDIM + col + 1];
            }
            if (layer < 3) {
                float* o = optr[layer];
                *reinterpret_cast<float2*>(o + (size_t)row0 * HDIM + col) =
                    make_float2(v0, v1);
                *reinterpret_cast<float2*>(o + (size_t)(row0 + 8) * HDIM + col) =
                    make_float2(v2, v3);
            } else {
#pragma unroll
                for (int l = 0; l < NLAYER; l++) {
                    const size_t b0i = (size_t)l * BH + (size_t)row0 * HDIM + col;
                    const size_t b1i = (size_t)l * BH + (size_t)(row0 + 8) * HDIM + col;
                    float2 h0 = *reinterpret_cast<const float2*>(hiddens + b0i);
                    float2 h8 = *reinterpret_cast<const float2*>(hiddens + b1i);
                    *reinterpret_cast<float2*>(hplus + b0i) =
                        make_float2(h0.x + v0, h0.y + v1);
                    *reinterpret_cast<float2*>(hplus + b1i) =
                        make_float2(h8.x + v2, h8.y + v3);
                }
            }
            fence_async();   // outputs are consumed via TMA (next layer / gh GEMM)
        }

        if (layer < 3) {
            __threadfence();
            __syncthreads();
            if (tid == 0) {
                atomicAdd(&g_bar2[layer], 1);
                while (atomicAdd(&g_bar2[layer], 0) < (int)gridDim.x) __nanosleep(32);
            }
            __syncthreads();
        }
    }
}

// ---------------- TMA GEMM v2: producer warp (288 threads) ----------
__global__ __launch_bounds__(288) void gemm_tma(
    const __grid_constant__ CUtensorMap mapA,
    const __grid_constant__ CUtensorMap mapW,
    const float* __restrict__ bias, float* __restrict__ out,
    int N, int biasStride) {
    constexpr int BN = 128;
    constexpr int STG = (64 + BN) * 32 * 4;   // 24576
    extern __shared__ float sm[];
    const uint32_t sb = (uint32_t)__cvta_generic_to_shared(sm);
    const uint32_t tiles = sb + 1024;

    const int tid = threadIdx.x, lane = tid & 31, warp = tid >> 5;
    const int wm = warp & 3, wn = (warp >> 2) & 1;
    const int r = lane >> 2, kk = lane & 3;
    const int nBlock = blockIdx.x * BN;
    const int layer = blockIdx.y;
    const bool producer = (warp == 8);

    bias += (size_t)layer * biasStride;
    out += (size_t)layer * BATCH * N;

    if (tid == 0) {
#pragma unroll
        for (int s = 0; s < 4; s++) {
            mbar_init(sb + s * 16, 1);
            mbar_init(sb + s * 16 + 8, 8);
        }
    }
    __syncthreads();

    if (producer && lane == 0) {
        for (int kt = 0; kt < 32; kt++) {
            const int s = kt & 3, n = kt >> 2;
            if (n > 0) mbar_wait(sb + s * 16 + 8, (n - 1) & 1);
            const uint32_t mb = sb + s * 16;
            mbar_expect(mb, STG);
            const uint32_t dA = tiles + s * STG;
            tma3(dA, &mapA, kt * 32, 0, layer, mb);
            tma3(dA + 64 * 128, &mapW, kt * 32, nBlock, layer, mb);
        }
        return;
    }
    if (producer) return;

    float acc[8][4];
#pragma unroll
    for (int i = 0; i < 8; i++)
#pragma unroll
        for (int j = 0; j < 4; j++) acc[i][j] = 0.f;

    const int swz = r << 2;
    for (int kt = 0; kt < 32; kt++) {
        const int s = kt & 3;
        mbar_wait(sb + s * 16, (kt >> 2) & 1);
        const float* a_ = sm + 256 + s * (STG / 4);
        const float* w_ = a_ + 64 * 32;
#pragma unroll
        for (int q = 0; q < 4; q++) {
            const int col = (q * 8 + kk) ^ swz;
            const int col4 = col ^ 4;
            const int m0 = wm * 16 + r;
            const uint32_t a0 = tfb(a_[m0 * 32 + col]);
            const uint32_t a1 = tfb(a_[(m0 + 8) * 32 + col]);
            const uint32_t a2 = tfb(a_[m0 * 32 + col4]);
            const uint32_t a3 = tfb(a_[(m0 + 8) * 32 + col4]);
#pragma unroll
            for (int nt = 0; nt < 8; nt++) {
                const int n = wn * 64 + nt * 8 + r;
                mma8(acc[nt], a0, a1, a2, a3, tfb(w_[n * 32 + col]),
                     tfb(w_[n * 32 + col4]));
            }
        }
        if (lane == 0) mbar_arrive(sb + s * 16 + 8);
    }

    const int row0 = wm * 16 + r;
#pragma unroll
    for (int nt = 0; nt < 8; nt++) {
        const int col = nBlock + wn * 64 + nt * 8 + 2 * kk;
        const float b0v = bias[col], b1v = bias[col + 1];
        *reinterpret_cast<float2*>(out + (size_t)row0 * N + col) =
            make_float2(acc[nt][0] + b0v, acc[nt][1] + b1v);
        *reinterpret_cast<float2*>(out + (size_t)(row0 + 8) * N + col) =
            make_float2(acc[nt][2] + b0v, acc[nt][3] + b1v);
    }
}

// ---------------- persistent fused GRU chain v9: dedicated producer warp ----------
__global__ __launch_bounds__(416) void gru_chain(
    const __grid_constant__ CUtensorMap mapA,
    const __grid_constant__ CUtensorMap mapW,
    float* __restrict__ ain, float* __restrict__ nh, float* __restrict__ h1,
    const float* __restrict__ gru_bih, const float* __restrict__ gh,
    const float* __restrict__ hplus) {
    constexpr int SLOT = 22528;
    constexpr int CLD = 26;
    extern __shared__ float sm[];
    const uint32_t sb = (uint32_t)__cvta_generic_to_shared(sm);
    const uint32_t tiles = sb + 1024;
    float* Cs = sm + 256 + 4 * (SLOT / 4);
    float* ghs = Cs + 64 * CLD;
    float* hps = ghs + 64 * 24;
    const uint32_t sGh = (uint32_t)__cvta_generic_to_shared(ghs);
    const uint32_t sHp = (uint32_t)__cvta_generic_to_shared(hps);

    const int g = blockIdx.x;
    const int h0 = g * 8;
    const int tid = threadIdx.x, lane = tid & 31, warp = tid >> 5;
    const int wm = warp & 3, sec = warp >> 2;
    const int r = lane >> 2, kk = lane & 3;
    const int swz = r << 2;
    const bool producer = (warp == 12);

    if (tid == 0) {
#pragma unroll
        for (int s = 0; s < 4; s++) {
            mbar_init(sb + s * 16, 2);
            mbar_init(sb + s * 16 + 8, 12);
        }
    }
    __syncthreads();

    auto fillW = [&](int gidx) {
        const int s = gidx & 3;
        const int n = gidx >> 2;
        if (n > 0) mbar_wait(sb + s * 16 + 8, (n - 1) & 1);
        const uint32_t mb = sb + s * 16;
        mbar_expect(mb, 6144);
        const int layer = gidx >> 4, kt = gidx & 15;
        const int x0 = kt * 64;
        const uint32_t dst = tiles + s * SLOT + 16384;
        tma4(dst, &mapW, x0, h0, 0, layer, mb);
        tma4(dst + 3072, &mapW, x0 + 32, h0, 0, layer, mb);
    };
    auto fillA = [&](int gidx) {
        const int s = gidx & 3;
        const uint32_t mb = sb + s * 16;
        mbar_expect(mb, 16384);
        const int layer = gidx >> 4, kt = gidx & 15;
        const int x0 = kt * 64;
        const uint32_t dst = tiles + s * SLOT;
        tma3(dst, &mapA, x0, 0, layer, mb);
        tma3(dst + 8192, &mapA, x0 + 32, 0, layer, mb);
    };

    if (producer && lane == 0) {
        fillW(0); fillA(0); fillW(1); fillA(1); fillW(2); fillA(2);
    }

    float prev[2];

    for (int layer = 0; layer < NLAYER; layer++) {
        const float* bih = gru_bih + (size_t)layer * 3 * HDIM;
        float* outh = nh + (size_t)layer * BH;
        float* ainN = ain + (size_t)(layer + 1) * BH;
        const int g0 = layer * 16;

        {
            const int pair = tid >> 1, half = tid & 1;
            if (pair < 192) {
                const int b = pair / 3, gate = pair % 3;
                cp16(sGh + (uint32_t)((b * 24 + gate * 8 + half * 4) * 4),
                     gh + (size_t)layer * BATCH * 3 * HDIM + (size_t)b * 3 * HDIM +
                         gate * HDIM + h0 + half * 4);
            }
            if (tid < 128) {
                const int b = tid >> 1, half = tid & 1;
                cp16(sHp + (uint32_t)((b * 8 + half * 4) * 4),
                     hplus + (size_t)layer * BH + (size_t)b * HDIM + h0 + half * 4);
            }
            cp_commit();
        }

        if (!producer) {
            float acc[4] = {0.f, 0.f, 0.f, 0.f};
            for (int kt = 0; kt < 16; kt++) {
                const int gidx = g0 + kt;
                const int s = gidx & 3;
                mbar_wait(sb + s * 16, (gidx >> 2) & 1);
                const float* stg = sm + 256 + s * (SLOT / 4);
#pragma unroll
                for (int q = 0; q < 8; q++) {
                    const int p = q >> 2;
                    const float* a_ = stg + p * 2048;
                    const float* w_ = stg + 4096 + p * 768;
                    const int col = ((q & 3) * 8 + kk) ^ swz;
                    const int col4 = col ^ 4;
                    const int m0 = wm * 16 + r;
                    const uint32_t a0 = tfb(a_[m0 * 32 + col]);
                    const uint32_t a1 = tfb(a_[(m0 + 8) * 32 + col]);
                    const uint32_t a2 = tfb(a_[m0 * 32 + col4]);
                    const uint32_t a3 = tfb(a_[(m0 + 8) * 32 + col4]);
                    const int brow = sec * 8 + r;
                    mma8(acc, a0, a1, a2, a3, tfb(w_[brow * 32 + col]),
                         tfb(w_[brow * 32 + col4]));
                }
                if (lane == 0) mbar_arrive(sb + s * 16 + 8);
            }
            const int row0 = wm * 16 + r;
            const int cl = sec * 8 + 2 * kk;
            *reinterpret_cast<float2*>(&Cs[row0 * CLD + cl]) =
                make_float2(acc[0], acc[1]);
            *reinterpret_cast<float2*>(&Cs[(row0 + 8) * CLD + cl]) =
                make_float2(acc[2], acc[3]);
        } else if (lane == 0) {
            for (int kt = 0; kt < 16; kt++) {
                if (layer == 0 && kt < 3) continue;
                const int gidx = g0 + kt;
                if (kt < 3) {
                    fillA(gidx);
                } else {
                    fillW(gidx); fillA(gidx);
                }
            }
            if (layer < NLAYER - 1) {
                fillW(g0 + 16); fillW(g0 + 17); fillW(g0 + 18);
            }
        }

        cp_wait<0>();
        __syncthreads();

        int t = 0;
        for (int idx = tid; idx < 512; idx += 416, t++) {
            const int b = idx >> 3, hh = idx & 7;
            const int h = h0 + hh;
            const float ir = Cs[b * CLD + hh] + bih[h];
            const float iz = Cs[b * CLD + 8 + hh] + bih[HDIM + h];
            const float in_ = Cs[b * CLD + 16 + hh] + bih[2 * HDIM + h];
            const float rr = 1.f / (1.f + expf(-(ir + ghs[b * 24 + hh])));
            const float zz = 1.f / (1.f + expf(-(iz + ghs[b * 24 + 8 + hh])));
            const float nn = tanhf(in_ + rr * ghs[b * 24 + 16 + hh]);
            const float hp = hps[b * 8 + hh];
            const float o = (1.f - zz) * nn + zz * hp;
            outh[(size_t)b * HDIM + h] = o;
            if (layer == 0) h1[(size_t)b * HDIM + h] = o;
            if (layer < NLAYER - 1) {
                const float nx = (layer < 2) ? o : (o + prev[t]);
                ainN[(size_t)b * HDIM + h] = nx;
            }
            prev[t] = o;
        }

        if (layer < NLAYER - 1) {
            __threadfence();
            fence_async();
            __syncthreads();
            if (tid == 0) {
                atomicAdd(&g_bar[layer], 1);
                while (atomicAdd(&g_bar[layer], 0) < (int)gridDim.x) __nanosleep(32);
            }
            __syncthreads();
        }
    }
}

// ---------------- 2-pass online log_softmax ----------------
__global__ __launch_bounds__(1024) void log_softmax_kernel(float* __restrict__ logits) {
    const int b = blockIdx.x;
    float* row = logits + (size_t)b * VDIM;
    __shared__ float smax[32], ssum[32];
    __shared__ float s_lse;
    const int lane = threadIdx.x & 31;
    const int wid = threadIdx.x >> 5;

    float m = -1e30f, s = 0.f;
    const float4* r4 = reinterpret_cast<const float4*>(row);
    for (int v = threadIdx.x; v < VDIM / 4; v += blockDim.x) {
        float4 x = r4[v];
#define ONE(val) { float d = (val) - m; \
        if (d > 0.f) { s = s * __expf(-d) + 1.f; m = (val); } else s += __expf(d); }
        ONE(x.x) ONE(x.y) ONE(x.z) ONE(x.w)
#undef ONE
    }
#pragma unroll
    for (int o = 16; o; o >>= 1) {
        float mo = __shfl_xor_sync(0xffffffffu, m, o);
        float so = __shfl_xor_sync(0xffffffffu, s, o);
        float mn = fmaxf(m, mo);
        s = s * __expf(m - mn) + so * __expf(mo - mn);
        m = mn;
    }
    if (lane == 0) { smax[wid] = m; ssum[wid] = s; }
    __syncthreads();
    if (wid == 0) {
        float mm = (lane < (blockDim.x >> 5)) ? smax[lane] : -1e30f;
        float ss = (lane < (blockDim.x >> 5)) ? ssum[lane] : 0.f;
#pragma unroll
        for (int o = 16; o; o >>= 1) {
            float mo = __shfl_xor_sync(0xffffffffu, mm, o);
            float so = __shfl_xor_sync(0xffffffffu, ss, o);
            float mn = fmaxf(mm, mo);
            ss = ss * __expf(mm - mn) + so * __expf(mo - mn);
            mm = mn;
        }
        if (lane == 0) s_lse = mm + logf(ss);
    }
    __syncthreads();
    const float lse = s_lse;
    float4* w4 = reinterpret_cast<float4*>(row);
    for (int v = threadIdx.x; v < VDIM / 4; v += blockDim.x) {
        float4 x = w4[v];
        x.x -= lse; x.y -= lse; x.z -= lse; x.w -= lse;
        w4[v] = x;
    }
}

// ---------------- host-side tensormap encoding ----------------
typedef CUresult (CUDAAPI* EncFn)(
    CUtensorMap*, CUtensorMapDataType, cuuint32_t, void*,
    const cuuint64_t*, const cuuint64_t*, const cuuint32_t*, const cuuint32_t*,
    CUtensorMapInterleave, CUtensorMapSwizzle, CUtensorMapL2promotion,
    CUtensorMapFloatOOBfill);

static void make_map3(EncFn enc, CUtensorMap* m, const void* p,
                      unsigned long long d0, unsigned long long d1,
                      unsigned long long d2, unsigned int b1) {
    cuuint64_t dims[3] = {d0, d1, d2};
    cuuint64_t strides[2] = {d0 * 4, d0 * d1 * 4};
    cuuint32_t box[3] = {32, b1, 1};
    cuuint32_t es[3] = {1, 1, 1};
    enc(m, CU_TENSOR_MAP_DATA_TYPE_FLOAT32, 3, (void*)p, dims, strides, box, es,
        CU_TENSOR_MAP_INTERLEAVE_NONE, CU_TENSOR_MAP_SWIZZLE_128B,
        CU_TENSOR_MAP_L2_PROMOTION_L2_128B, CU_TENSOR_MAP_FLOAT_OOB_FILL_NONE);
}

static void make_map4_wih(EncFn enc, CUtensorMap* m, const void* p) {
    cuuint64_t dims[4] = {EDIM, HDIM, 3, NLAYER};
    cuuint64_t strides[3] = {(cuuint64_t)EDIM * 4,
                             (cuuint64_t)HDIM * EDIM * 4,
                             (cuuint64_t)3 * HDIM * EDIM * 4};
    cuuint32_t box[4] = {32, 8, 3, 1};
    cuuint32_t es[4] = {1, 1, 1, 1};
    enc(m, CU_TENSOR_MAP_DATA_TYPE_FLOAT32, 4, (void*)p, dims, strides, box, es,
        CU_TENSOR_MAP_INTERLEAVE_NONE, CU_TENSOR_MAP_SWIZZLE_128B,
        CU_TENSOR_MAP_L2_PROMOTION_L2_128B, CU_TENSOR_MAP_FLOAT_OOB_FILL_NONE);
}

// ---------------- launch ----------------
extern "C" void kernel_launch(void* const* d_in, const int* in_sizes, int n_in,
                              void* d_out, int out_size) {
    const float* feature   = (const float*)d_in[0];
    const int*   x         = (const int*)d_in[1];
    const float* attention = (const float*)d_in[2];
    const float* hiddens   = (const float*)d_in[3];
    const float* emb       = (const float*)d_in[4];
    const float* map_W     = (const float*)d_in[5];
    const float* map_b     = (const float*)d_in[6];
    const float* ai_W      = (const float*)d_in[7];
    const float* ai_b      = (const float*)d_in[8];
    const float* ah_W      = (const float*)d_in[9];
    const float* ah_b      = (const float*)d_in[10];
    const float* ao_W      = (const float*)d_in[11];
    const float* ao_b      = (const float*)d_in[12];
    const float* gru_Wih   = (const float*)d_in[13];
    const float* gru_Whh   = (const float*)d_in[14];
    const float* gru_bih   = (const float*)d_in[15];
    const float* gru_bhh   = (const float*)d_in[16];
    const float* out_W     = (const float*)d_in[17];
    const float* out_b     = (const float*)d_in[18];

    float* out = (float*)d_out;
    float* logp = out;
    float* h1   = out + (size_t)BATCH * VDIM;
    float* nh   = h1 + (size_t)BATCH * HDIM;

    float *ain, *buf0, *buf1, *gh, *hplus;
    cudaGetSymbolAddress((void**)&ain, g_ain);
    cudaGetSymbolAddress((void**)&buf0, g_buf0);
    cudaGetSymbolAddress((void**)&buf1, g_buf1);
    cudaGetSymbolAddress((void**)&gh, g_gh);
    cudaGetSymbolAddress((void**)&hplus, g_hplus);

    EncFn enc = nullptr;
    cudaDriverEntryPointQueryResult qr;
    cudaGetDriverEntryPoint("cuTensorMapEncodeTiled", (void**)&enc,
                            cudaEnableDefault, &qr);
    CUtensorMap mW_gh, mA_gh, mW_out, mA_out, mA_ch, mW_ch;
    CUtensorMap mFeat, mB0, mB1, mW0, mW1, mW2, mW3;
    make_map3(enc, &mW_gh, gru_Whh, HDIM, 3 * HDIM, NLAYER, 128);
    make_map3(enc, &mA_gh, hplus, HDIM, BATCH, NLAYER, 64);
    make_map3(enc, &mW_out, out_W, HDIM, VDIM, 1, 128);
    make_map3(enc, &mA_out, nh + 7 * (size_t)BH, HDIM, BATCH, 1, 64);
    make_map3(enc, &mA_ch, ain, EDIM, BATCH, NLAYER, 64);
    make_map4_wih(enc, &mW_ch, gru_Wih);
    make_map3(enc, &mFeat, feature, FDIM, BATCH, 1, 64);
    make_map3(enc, &mB0, buf0, HDIM, BATCH, 1, 64);
    make_map3(enc, &mB1, buf1, HDIM, BATCH, 1, 64);
    make_map3(enc, &mW0, map_W, FDIM, HDIM, 1, 16);
    make_map3(enc, &mW1, ai_W, HDIM, HDIM, 1, 16);
    make_map3(enc, &mW2, ah_W, HDIM, HDIM, 1, 16);
    make_map3(enc, &mW3, ao_W, HDIM, HDIM, 1, 16);

    const int SM_TMA = 1024 + 4 * (64 + 128) * 32 * 4;                        // 99328
    const int SM_CH  = 1024 + 4 * 22528 + (64 * 26 + 64 * 24 + 64 * 8) * 4;  // 105984
    const int SM_ATT = 1024 + 4 * 20480;                                      // 82944
    cudaFuncSetAttribute((const void*)gemm_tma,
                         cudaFuncAttributeMaxDynamicSharedMemorySize, SM_TMA);
    cudaFuncSetAttribute((const void*)gru_chain,
                         cudaFuncAttributeMaxDynamicSharedMemorySize, SM_CH);
    cudaFuncSetAttribute((const void*)attn_chain,
                         cudaFuncAttributeMaxDynamicSharedMemorySize, SM_ATT);

    // 1) embed into ain[0] (+ barrier init)
    embed_relu_kernel<<<BATCH, 256>>>(emb, x, ain);

    // 2) attention chain via TMA + producer warp (64 CTAs); writes hplus
    attn_chain<<<HDIM / 16, 288, SM_ATT>>>(mFeat, mB0, mB1, mW0, mW1, mW2, mW3,
                                           attention, map_b, ai_b, ah_b, ao_b,
                                           buf0, buf1, hiddens, hplus);

    // 3) all 8 gh GEMMs via TMA + producer warp (192 CTAs)
    gemm_tma<<<dim3(3 * HDIM / 128, NLAYER), 288, SM_TMA>>>(
        mA_gh, mW_gh, gru_bhh, gh, 3 * HDIM, 3 * HDIM);

    // 4) persistent GRU chain with dedicated producer warp (128 CTAs x 416 thr)
    gru_chain<<<128, 416, SM_CH>>>(mA_ch, mW_ch, ain, nh, h1,
                                   gru_bih, gh, hplus);

    // 5) output projection via TMA + producer warp (250 CTAs) + log-softmax
    gemm_tma<<<dim3(VDIM / 128, 1), 288, SM_TMA>>>(
        mA_out, mW_out, out_b, logp, VDIM, 0);
    log_softmax_kernel<<<BATCH, 1024>>>(logp);
}